// round 1
// baseline (speedup 1.0000x reference)
#include <cuda_runtime.h>
#include <math.h>

#define T_TOK 4096
#define DDIM  2048
#define NEXP  8
#define FDIM  512
#define CAP   4096

// Scratch (device globals: no allocation allowed in kernel_launch)
__device__ float g_inter[(size_t)NEXP * CAP * FDIM];   // routed SwiGLU output per (expert, slot)
__device__ float g_sinter[(size_t)T_TOK * FDIM];       // shared-expert SwiGLU output
__device__ int   g_cnt[NEXP];
__device__ int   g_tok[NEXP * CAP];
__device__ float g_wt[NEXP * CAP];
__device__ float g_gate[T_TOK];

__global__ void zero_counts_kernel() {
    if (threadIdx.x < NEXP) g_cnt[threadIdx.x] = 0;
}

// ---------------------------------------------------------------------------
// Router: 1 warp per token. 9 dot products (8 experts + shared gate vector).
// Writes full logits, picks top-2 (lowest-index tie-break, like jax top_k),
// pairwise-softmax weights, builds per-expert token lists.
// ---------------------------------------------------------------------------
__global__ void router_kernel(const float* __restrict__ h,
                              const float* __restrict__ gate_w,
                              const float* __restrict__ sg_w,
                              float* __restrict__ logits_out) {
    int warp = threadIdx.x >> 5;
    int lane = threadIdx.x & 31;
    int t = blockIdx.x * 4 + warp;
    if (t >= T_TOK) return;

    float acc[9];
#pragma unroll
    for (int i = 0; i < 9; i++) acc[i] = 0.f;

    const float* hp = h + (size_t)t * DDIM;
    for (int d = lane; d < DDIM; d += 32) {
        float hv = hp[d];
#pragma unroll
        for (int e = 0; e < NEXP; e++) acc[e] += hv * gate_w[e * DDIM + d];
        acc[8] += hv * sg_w[d];
    }
#pragma unroll
    for (int i = 0; i < 9; i++) {
#pragma unroll
        for (int off = 16; off > 0; off >>= 1)
            acc[i] += __shfl_down_sync(0xffffffffu, acc[i], off);
    }

    if (lane == 0) {
        if (logits_out) {
#pragma unroll
            for (int e = 0; e < NEXP; e++) logits_out[t * NEXP + e] = acc[e];
        }
        int i0 = 0;
#pragma unroll
        for (int e = 1; e < NEXP; e++) if (acc[e] > acc[i0]) i0 = e;
        int i1 = (i0 == 0) ? 1 : 0;
#pragma unroll
        for (int e = 0; e < NEXP; e++) if (e != i0 && acc[e] > acc[i1]) i1 = e;

        // normalized top-2 softmax weights (full-softmax denominator cancels)
        float wA = 1.f / (1.f + expf(acc[i1] - acc[i0]));
        float wB = 1.f - wA;

        int s0 = atomicAdd(&g_cnt[i0], 1);
        g_tok[i0 * CAP + s0] = t;  g_wt[i0 * CAP + s0] = wA;
        int s1 = atomicAdd(&g_cnt[i1], 1);
        g_tok[i1 * CAP + s1] = t;  g_wt[i1 * CAP + s1] = wB;

        g_gate[t] = 1.f / (1.f + expf(-acc[8]));
    }
}

// ---------------------------------------------------------------------------
// Routed up-projection: per expert, gathered GEMM [Ne,D]x[D,F] for W0 and W1
// simultaneously, SiLU(g)*u epilogue -> g_inter.
// Tile: 64x64, BK=16, 256 threads, 4x4 micro-tile, dual accumulators.
// ---------------------------------------------------------------------------
__global__ void up_routed_kernel(const float* __restrict__ h,
                                 const float* __restrict__ w0, const float* __restrict__ b0,
                                 const float* __restrict__ w1, const float* __restrict__ b1) {
    const int e   = blockIdx.z;
    const int Ne  = g_cnt[e];
    const int row0 = blockIdx.y * 64;
    if (row0 >= Ne) return;
    const int n0  = blockIdx.x * 64;
    const int tid = threadIdx.x;
    const int tx = tid & 15, ty = tid >> 4;

    __shared__ int   sTok[64];
    __shared__ float As[16][68];
    __shared__ float Bs0[16][68];
    __shared__ float Bs1[16][68];

    if (tid < 64) {
        int r = row0 + tid;
        sTok[tid] = g_tok[e * CAP + (r < Ne ? r : Ne - 1)];
    }
    __syncthreads();

    const float* w0p = w0 + (size_t)e * FDIM * DDIM;
    const float* w1p = w1 + (size_t)e * FDIM * DDIM;

    float accg[16], accu[16];
#pragma unroll
    for (int i = 0; i < 16; i++) { accg[i] = 0.f; accu[i] = 0.f; }

    for (int kt = 0; kt < DDIM; kt += 16) {
#pragma unroll
        for (int i = 0; i < 4; i++) {
            int idx = tid + i * 256;
            int r = idx >> 4, k = idx & 15;
            As[k][r]  = h[(size_t)sTok[r] * DDIM + kt + k];
            Bs0[k][r] = w0p[(size_t)(n0 + r) * DDIM + kt + k];
            Bs1[k][r] = w1p[(size_t)(n0 + r) * DDIM + kt + k];
        }
        __syncthreads();
#pragma unroll
        for (int kk = 0; kk < 16; kk++) {
            float4 av  = *reinterpret_cast<const float4*>(&As[kk][ty * 4]);
            float4 g4  = *reinterpret_cast<const float4*>(&Bs0[kk][tx * 4]);
            float4 u4  = *reinterpret_cast<const float4*>(&Bs1[kk][tx * 4]);
            float a[4]  = {av.x, av.y, av.z, av.w};
            float bg[4] = {g4.x, g4.y, g4.z, g4.w};
            float bu[4] = {u4.x, u4.y, u4.z, u4.w};
#pragma unroll
            for (int i = 0; i < 4; i++)
#pragma unroll
                for (int j = 0; j < 4; j++) {
                    accg[i * 4 + j] += a[i] * bg[j];
                    accu[i * 4 + j] += a[i] * bu[j];
                }
        }
        __syncthreads();
    }

    float* outp = g_inter + (size_t)e * CAP * FDIM;
#pragma unroll
    for (int i = 0; i < 4; i++) {
        int r = row0 + ty * 4 + i;
        if (r >= Ne) continue;
#pragma unroll
        for (int j = 0; j < 4; j++) {
            int f = n0 + tx * 4 + j;
            float gg = accg[i * 4 + j] + b0[e * FDIM + f];
            float uu = accu[i * 4 + j] + b1[e * FDIM + f];
            float sg = gg / (1.f + expf(-gg));
            outp[(size_t)r * FDIM + f] = sg * uu;
        }
    }
}

// ---------------------------------------------------------------------------
// Shared-expert up-projection (identity gather, Ne = T)
// ---------------------------------------------------------------------------
__global__ void up_shared_kernel(const float* __restrict__ h,
                                 const float* __restrict__ sw0, const float* __restrict__ sb0,
                                 const float* __restrict__ sw1, const float* __restrict__ sb1) {
    const int row0 = blockIdx.y * 64;
    const int n0   = blockIdx.x * 64;
    const int tid = threadIdx.x;
    const int tx = tid & 15, ty = tid >> 4;

    __shared__ float As[16][68];
    __shared__ float Bs0[16][68];
    __shared__ float Bs1[16][68];

    float accg[16], accu[16];
#pragma unroll
    for (int i = 0; i < 16; i++) { accg[i] = 0.f; accu[i] = 0.f; }

    for (int kt = 0; kt < DDIM; kt += 16) {
#pragma unroll
        for (int i = 0; i < 4; i++) {
            int idx = tid + i * 256;
            int r = idx >> 4, k = idx & 15;
            As[k][r]  = h[(size_t)(row0 + r) * DDIM + kt + k];
            Bs0[k][r] = sw0[(size_t)(n0 + r) * DDIM + kt + k];
            Bs1[k][r] = sw1[(size_t)(n0 + r) * DDIM + kt + k];
        }
        __syncthreads();
#pragma unroll
        for (int kk = 0; kk < 16; kk++) {
            float4 av  = *reinterpret_cast<const float4*>(&As[kk][ty * 4]);
            float4 g4  = *reinterpret_cast<const float4*>(&Bs0[kk][tx * 4]);
            float4 u4  = *reinterpret_cast<const float4*>(&Bs1[kk][tx * 4]);
            float a[4]  = {av.x, av.y, av.z, av.w};
            float bg[4] = {g4.x, g4.y, g4.z, g4.w};
            float bu[4] = {u4.x, u4.y, u4.z, u4.w};
#pragma unroll
            for (int i = 0; i < 4; i++)
#pragma unroll
                for (int j = 0; j < 4; j++) {
                    accg[i * 4 + j] += a[i] * bg[j];
                    accu[i * 4 + j] += a[i] * bu[j];
                }
        }
        __syncthreads();
    }

#pragma unroll
    for (int i = 0; i < 4; i++) {
        int r = row0 + ty * 4 + i;
#pragma unroll
        for (int j = 0; j < 4; j++) {
            int f = n0 + tx * 4 + j;
            float gg = accg[i * 4 + j] + sb0[f];
            float uu = accu[i * 4 + j] + sb1[f];
            float sg = gg / (1.f + expf(-gg));
            g_sinter[(size_t)r * FDIM + f] = sg * uu;
        }
    }
}

// ---------------------------------------------------------------------------
// Shared-expert down-projection: WRITES the output base
// out[t,d] = gate[t] * (sinter[t]·swo[d] + sbo[d])
// ---------------------------------------------------------------------------
__global__ void down_shared_kernel(const float* __restrict__ swo,
                                   const float* __restrict__ sbo,
                                   float* __restrict__ out) {
    const int row0 = blockIdx.y * 64;
    const int n0   = blockIdx.x * 64;   // over D
    const int tid = threadIdx.x;
    const int tx = tid & 15, ty = tid >> 4;

    __shared__ float As[16][68];
    __shared__ float Bs[16][68];

    float acc[16];
#pragma unroll
    for (int i = 0; i < 16; i++) acc[i] = 0.f;

    for (int kt = 0; kt < FDIM; kt += 16) {
#pragma unroll
        for (int i = 0; i < 4; i++) {
            int idx = tid + i * 256;
            int r = idx >> 4, k = idx & 15;
            As[k][r] = g_sinter[(size_t)(row0 + r) * FDIM + kt + k];
            Bs[k][r] = swo[(size_t)(n0 + r) * FDIM + kt + k];
        }
        __syncthreads();
#pragma unroll
        for (int kk = 0; kk < 16; kk++) {
            float4 av = *reinterpret_cast<const float4*>(&As[kk][ty * 4]);
            float4 bv = *reinterpret_cast<const float4*>(&Bs[kk][tx * 4]);
            float a[4] = {av.x, av.y, av.z, av.w};
            float b[4] = {bv.x, bv.y, bv.z, bv.w};
#pragma unroll
            for (int i = 0; i < 4; i++)
#pragma unroll
                for (int j = 0; j < 4; j++)
                    acc[i * 4 + j] += a[i] * b[j];
        }
        __syncthreads();
    }

#pragma unroll
    for (int i = 0; i < 4; i++) {
        int t = row0 + ty * 4 + i;
        float gate = g_gate[t];
#pragma unroll
        for (int j = 0; j < 4; j++) {
            int d = n0 + tx * 4 + j;
            out[(size_t)t * DDIM + d] = gate * (acc[i * 4 + j] + sbo[d]);
        }
    }
}

// ---------------------------------------------------------------------------
// Routed down-projection + weighted scatter:
// out[t,d] += wt * (inter[e,slot]·wo[e,d] + bo[e,d])   (atomicAdd)
// ---------------------------------------------------------------------------
__global__ void down_routed_kernel(const float* __restrict__ wo,
                                   const float* __restrict__ bo,
                                   float* __restrict__ out) {
    const int e   = blockIdx.z;
    const int Ne  = g_cnt[e];
    const int row0 = blockIdx.y * 64;
    if (row0 >= Ne) return;
    const int n0  = blockIdx.x * 64;   // over D
    const int tid = threadIdx.x;
    const int tx = tid & 15, ty = tid >> 4;

    __shared__ int   sTok[64];
    __shared__ float sWt[64];
    __shared__ float As[16][68];
    __shared__ float Bs[16][68];

    if (tid < 64) {
        int r = row0 + tid;
        int rr = (r < Ne ? r : Ne - 1);
        sTok[tid] = g_tok[e * CAP + rr];
        sWt[tid]  = g_wt[e * CAP + rr];
    }
    __syncthreads();

    const float* Ap = g_inter + (size_t)e * CAP * FDIM;
    const float* Bp = wo + (size_t)e * DDIM * FDIM;

    float acc[16];
#pragma unroll
    for (int i = 0; i < 16; i++) acc[i] = 0.f;

    for (int kt = 0; kt < FDIM; kt += 16) {
#pragma unroll
        for (int i = 0; i < 4; i++) {
            int idx = tid + i * 256;
            int r = idx >> 4, k = idx & 15;
            As[k][r] = Ap[(size_t)(row0 + r) * FDIM + kt + k];
            Bs[k][r] = Bp[(size_t)(n0 + r) * FDIM + kt + k];
        }
        __syncthreads();
#pragma unroll
        for (int kk = 0; kk < 16; kk++) {
            float4 av = *reinterpret_cast<const float4*>(&As[kk][ty * 4]);
            float4 bv = *reinterpret_cast<const float4*>(&Bs[kk][tx * 4]);
            float a[4] = {av.x, av.y, av.z, av.w};
            float b[4] = {bv.x, bv.y, bv.z, bv.w};
#pragma unroll
            for (int i = 0; i < 4; i++)
#pragma unroll
                for (int j = 0; j < 4; j++)
                    acc[i * 4 + j] += a[i] * b[j];
        }
        __syncthreads();
    }

#pragma unroll
    for (int i = 0; i < 4; i++) {
        int r = row0 + ty * 4 + i;
        if (r >= Ne) continue;
        int   t  = sTok[ty * 4 + i];
        float wt = sWt[ty * 4 + i];
#pragma unroll
        for (int j = 0; j < 4; j++) {
            int d = n0 + tx * 4 + j;
            float v = wt * (acc[i * 4 + j] + bo[e * DDIM + d]);
            atomicAdd(&out[(size_t)t * DDIM + d], v);
        }
    }
}

// ---------------------------------------------------------------------------
extern "C" void kernel_launch(void* const* d_in, const int* in_sizes, int n_in,
                              void* d_out, int out_size) {
    const float* h      = (const float*)d_in[0];
    const float* gate_w = (const float*)d_in[1];
    const float* w0     = (const float*)d_in[2];
    const float* b0     = (const float*)d_in[3];
    const float* w1     = (const float*)d_in[4];
    const float* b1     = (const float*)d_in[5];
    const float* wo     = (const float*)d_in[6];
    const float* bo     = (const float*)d_in[7];
    const float* sw0    = (const float*)d_in[8];
    const float* sb0    = (const float*)d_in[9];
    const float* sw1    = (const float*)d_in[10];
    const float* sb1    = (const float*)d_in[11];
    const float* swo    = (const float*)d_in[12];
    const float* sbo    = (const float*)d_in[13];
    const float* sg_w   = (const float*)d_in[14];

    float* out = (float*)d_out;
    // Output layout assumption: [final (T*D) | router_logits (T*E)].
    float* logits = nullptr;
    if ((size_t)out_size >= (size_t)T_TOK * DDIM + (size_t)T_TOK * NEXP)
        logits = out + (size_t)T_TOK * DDIM;

    zero_counts_kernel<<<1, 32>>>();
    router_kernel<<<T_TOK / 4, 128>>>(h, gate_w, sg_w, logits);
    up_routed_kernel<<<dim3(FDIM / 64, CAP / 64, NEXP), 256>>>(h, w0, b0, w1, b1);
    up_shared_kernel<<<dim3(FDIM / 64, T_TOK / 64, 1), 256>>>(h, sw0, sb0, sw1, sb1);
    down_shared_kernel<<<dim3(DDIM / 64, T_TOK / 64, 1), 256>>>(swo, sbo, out);
    down_routed_kernel<<<dim3(DDIM / 64, CAP / 64, NEXP), 256>>>(wo, bo, out);
}

// round 4
// speedup vs baseline: 2.5577x; 2.5577x over previous
#include <cuda_runtime.h>
#include <math.h>
#include <stdint.h>

#define T_TOK 4096
#define DDIM  2048
#define NEXP  8
#define FDIM  512
#define CAP   4096
#define BM    128
#define BN    128
#define BK    16
#define SPAD  20     // smem row stride in words (BK + 4, conflict-free)

// ---------------------------------------------------------------------------
// Scratch (device globals; allocation is forbidden)
// ---------------------------------------------------------------------------
__device__ float g_gbuf[(size_t)NEXP * CAP * FDIM];  // routed: g, then silu(g)*u
__device__ float g_ubuf[(size_t)NEXP * CAP * FDIM];  // routed: u
__device__ float g_sg[(size_t)T_TOK * FDIM];         // shared: g, then silu(g)*u
__device__ float g_su[(size_t)T_TOK * FDIM];         // shared: u
__device__ int   g_cnt[NEXP];
__device__ int   g_tok[NEXP * CAP];
__device__ float g_wt[NEXP * CAP];
__device__ float g_gate[T_TOK];

__device__ __forceinline__ uint32_t tf32r(float f) {
    uint32_t r; asm("cvt.rna.tf32.f32 %0, %1;" : "=r"(r) : "f"(f)); return r;
}
__device__ __forceinline__ void mma8(float* d, const uint32_t* a, const uint32_t* b) {
    asm volatile(
        "mma.sync.aligned.m16n8k8.row.col.f32.tf32.tf32.f32 "
        "{%0,%1,%2,%3}, {%4,%5,%6,%7}, {%8,%9}, {%0,%1,%2,%3};"
        : "+f"(d[0]), "+f"(d[1]), "+f"(d[2]), "+f"(d[3])
        : "r"(a[0]), "r"(a[1]), "r"(a[2]), "r"(a[3]), "r"(b[0]), "r"(b[1]));
}

// ---------------------------------------------------------------------------
__global__ void zero_counts_kernel() {
    if (threadIdx.x < NEXP) g_cnt[threadIdx.x] = 0;
}

// ---------------------------------------------------------------------------
// Router: 1 warp per token. Full logits to out tail, top-2 (low-index ties),
// pairwise-softmax weights, per-expert token lists, shared sigmoid gate.
// ---------------------------------------------------------------------------
__global__ void router_kernel(const float* __restrict__ h,
                              const float* __restrict__ gate_w,
                              const float* __restrict__ sg_w,
                              float* __restrict__ logits_out) {
    int warp = threadIdx.x >> 5;
    int lane = threadIdx.x & 31;
    int t = blockIdx.x * 4 + warp;
    if (t >= T_TOK) return;

    float acc[9];
#pragma unroll
    for (int i = 0; i < 9; i++) acc[i] = 0.f;

    const float4* hp = (const float4*)(h + (size_t)t * DDIM);
    for (int d = lane; d < DDIM / 4; d += 32) {
        float4 hv = hp[d];
#pragma unroll
        for (int e = 0; e < NEXP; e++) {
            float4 w = ((const float4*)(gate_w + (size_t)e * DDIM))[d];
            acc[e] += hv.x * w.x + hv.y * w.y + hv.z * w.z + hv.w * w.w;
        }
        float4 w = ((const float4*)sg_w)[d];
        acc[8] += hv.x * w.x + hv.y * w.y + hv.z * w.z + hv.w * w.w;
    }
#pragma unroll
    for (int i = 0; i < 9; i++) {
#pragma unroll
        for (int off = 16; off > 0; off >>= 1)
            acc[i] += __shfl_down_sync(0xffffffffu, acc[i], off);
    }

    if (lane == 0) {
        if (logits_out) {
#pragma unroll
            for (int e = 0; e < NEXP; e++) logits_out[t * NEXP + e] = acc[e];
        }
        int i0 = 0;
#pragma unroll
        for (int e = 1; e < NEXP; e++) if (acc[e] > acc[i0]) i0 = e;
        int i1 = (i0 == 0) ? 1 : 0;
#pragma unroll
        for (int e = 0; e < NEXP; e++) if (e != i0 && e != i1 && acc[e] > acc[i1]) i1 = e;

        float wA = 1.f / (1.f + expf(acc[i1] - acc[i0]));
        float wB = 1.f - wA;

        int s0 = atomicAdd(&g_cnt[i0], 1);
        g_tok[i0 * CAP + s0] = t;  g_wt[i0 * CAP + s0] = wA;
        int s1 = atomicAdd(&g_cnt[i1], 1);
        g_tok[i1 * CAP + s1] = t;  g_wt[i1 * CAP + s1] = wB;

        g_gate[t] = 1.f / (1.f + expf(-acc[8]));
    }
}

// ---------------------------------------------------------------------------
// Generic tf32 mma.sync GEMM: C[m,n] = sum_k A[m,k]*B[n,k] (+bias), 4 modes.
// MODE 0: up-routed   A = h gathered by token list; out[slot,f] = acc + b[e,f]
// MODE 1: up-shared   A = h direct;                 out[t,f]    = acc + b[f]
// MODE 2: down-routed A = g_gbuf by slot; atomicAdd(out[tok,d], wt*(acc+bo[e,d]))
// MODE 3: down-shared A = g_sg direct;    out[t,d] = gate[t]*(acc+sbo[d])
// CTA tile 128x128, BK=16, 256 threads (8 warps, 2x4 -> 64x32 per warp).
// ---------------------------------------------------------------------------
template<int MODE>
__global__ void __launch_bounds__(256)
gemm_tc(const float* __restrict__ A, const float* __restrict__ B,
        const float* __restrict__ bias, float* __restrict__ out) {
    constexpr int K = (MODE < 2) ? DDIM : FDIM;
    const int e  = (MODE == 0 || MODE == 2) ? blockIdx.z : 0;
    const int Ne = (MODE == 0 || MODE == 2) ? g_cnt[e] : T_TOK;
    const int row0 = blockIdx.y * BM;
    if (row0 >= Ne) return;
    const int n0  = blockIdx.x * BN;
    const int tid  = threadIdx.x;
    const int lane = tid & 31;
    const int wid  = tid >> 5;
    const int wm   = (wid >> 2) * 64;   // warp m offset
    const int wn   = (wid & 3) * 32;    // warp n offset

    __shared__ uint32_t As[BM][SPAD];
    __shared__ uint32_t Bs[BN][SPAD];
    __shared__ int   sTok[BM];
    __shared__ float sWt[BM];

    if ((MODE == 0 || MODE == 2) && tid < BM) {
        int r = row0 + tid;
        int rr = (r < Ne) ? r : (Ne - 1);
        sTok[tid] = g_tok[e * CAP + rr];
        sWt[tid]  = g_wt[e * CAP + rr];
    }
    __syncthreads();

    // B base (rows = output cols, row-major [n, K])
    const float* Bb = (MODE == 0) ? (B + (size_t)e * FDIM * DDIM)
                    : (MODE == 2) ? (B + (size_t)e * DDIM * FDIM)
                    : B;

    float acc[4][4][4];
#pragma unroll
    for (int i = 0; i < 4; i++)
#pragma unroll
        for (int j = 0; j < 4; j++)
#pragma unroll
            for (int r = 0; r < 4; r++) acc[i][j][r] = 0.f;

    for (int kt = 0; kt < K; kt += BK) {
        // ---- stage tiles: 512 float4 per tile, 2 per thread ----
#pragma unroll
        for (int i = 0; i < 2; i++) {
            int q  = tid + i * 256;
            int r  = q >> 2;
            int c4 = (q & 3) * 4;
            const float* ap;
            if (MODE == 0)      ap = A + (size_t)sTok[r] * DDIM + kt + c4;
            else if (MODE == 1) ap = A + (size_t)(row0 + r) * DDIM + kt + c4;
            else if (MODE == 2) ap = A + ((size_t)e * CAP + row0 + r) * FDIM + kt + c4;
            else                ap = A + (size_t)(row0 + r) * FDIM + kt + c4;
            float4 v = *(const float4*)ap;
            *(uint4*)&As[r][c4] = make_uint4(tf32r(v.x), tf32r(v.y), tf32r(v.z), tf32r(v.w));

            const float* bp = Bb + (size_t)(n0 + r) * K + kt + c4;
            float4 w = *(const float4*)bp;
            *(uint4*)&Bs[r][c4] = make_uint4(tf32r(w.x), tf32r(w.y), tf32r(w.z), tf32r(w.w));
        }
        __syncthreads();

        // ---- compute: 2 k-steps of m16n8k8 ----
#pragma unroll
        for (int ks = 0; ks < BK; ks += 8) {
            uint32_t af[4][4], bf[4][2];
            const int lr = lane >> 2, lc = lane & 3;
#pragma unroll
            for (int im = 0; im < 4; im++) {
                int rb = wm + im * 16 + lr;
                af[im][0] = As[rb][ks + lc];
                af[im][1] = As[rb + 8][ks + lc];
                af[im][2] = As[rb][ks + lc + 4];
                af[im][3] = As[rb + 8][ks + lc + 4];
            }
#pragma unroll
            for (int in = 0; in < 4; in++) {
                int nb = wn + in * 8 + lr;
                bf[in][0] = Bs[nb][ks + lc];
                bf[in][1] = Bs[nb][ks + lc + 4];
            }
#pragma unroll
            for (int im = 0; im < 4; im++)
#pragma unroll
                for (int in = 0; in < 4; in++)
                    mma8(acc[im][in], af[im], bf[in]);
        }
        __syncthreads();
    }

    // ---- epilogue ----
    const float* bp = (MODE == 0) ? (bias + e * FDIM)
                    : (MODE == 2) ? (bias + e * DDIM)
                    : bias;
#pragma unroll
    for (int im = 0; im < 4; im++) {
#pragma unroll
        for (int in = 0; in < 4; in++) {
#pragma unroll
            for (int rg = 0; rg < 4; rg++) {
                int r = wm + im * 16 + (lane >> 2) + ((rg & 2) ? 8 : 0);
                int c = wn + in * 8 + 2 * (lane & 3) + (rg & 1);
                if (row0 + r >= Ne) continue;
                float v = acc[im][in][rg];
                int col = n0 + c;
                if (MODE == 0) {
                    out[((size_t)e * CAP + row0 + r) * FDIM + col] = v + bp[col];
                } else if (MODE == 1) {
                    out[(size_t)(row0 + r) * FDIM + col] = v + bp[col];
                } else if (MODE == 2) {
                    int   t  = sTok[r];
                    float wt = sWt[r];
                    atomicAdd(out + (size_t)t * DDIM + col, wt * (v + bp[col]));
                } else {
                    out[(size_t)(row0 + r) * DDIM + col] =
                        g_gate[row0 + r] * (v + bp[col]);
                }
            }
        }
    }
}

// ---------------------------------------------------------------------------
// SwiGLU elementwise: buf_g = silu(buf_g) * buf_u (float4, valid rows only)
// ---------------------------------------------------------------------------
__global__ void swiglu_routed_kernel() {
    size_t i = (size_t)blockIdx.x * 256 + threadIdx.x;   // float4 index
    size_t row = i >> 7;                                  // FDIM/4 = 128 per row
    int e = (int)(row >> 12);                             // CAP = 4096 rows/expert
    int slot = (int)(row & (CAP - 1));
    if (slot >= g_cnt[e]) return;
    float4 g = ((float4*)g_gbuf)[i];
    float4 u = ((float4*)g_ubuf)[i];
    g.x = g.x / (1.f + expf(-g.x)) * u.x;
    g.y = g.y / (1.f + expf(-g.y)) * u.y;
    g.z = g.z / (1.f + expf(-g.z)) * u.z;
    g.w = g.w / (1.f + expf(-g.w)) * u.w;
    ((float4*)g_gbuf)[i] = g;
}

__global__ void swiglu_shared_kernel() {
    size_t i = (size_t)blockIdx.x * 256 + threadIdx.x;
    float4 g = ((float4*)g_sg)[i];
    float4 u = ((float4*)g_su)[i];
    g.x = g.x / (1.f + expf(-g.x)) * u.x;
    g.y = g.y / (1.f + expf(-g.y)) * u.y;
    g.z = g.z / (1.f + expf(-g.z)) * u.z;
    g.w = g.w / (1.f + expf(-g.w)) * u.w;
    ((float4*)g_sg)[i] = g;
}

// ---------------------------------------------------------------------------
extern "C" void kernel_launch(void* const* d_in, const int* in_sizes, int n_in,
                              void* d_out, int out_size) {
    const float* h      = (const float*)d_in[0];
    const float* gate_w = (const float*)d_in[1];
    const float* w0     = (const float*)d_in[2];
    const float* b0     = (const float*)d_in[3];
    const float* w1     = (const float*)d_in[4];
    const float* b1     = (const float*)d_in[5];
    const float* wo     = (const float*)d_in[6];
    const float* bo     = (const float*)d_in[7];
    const float* sw0    = (const float*)d_in[8];
    const float* sb0    = (const float*)d_in[9];
    const float* sw1    = (const float*)d_in[10];
    const float* sb1    = (const float*)d_in[11];
    const float* swo    = (const float*)d_in[12];
    const float* sbo    = (const float*)d_in[13];
    const float* sg_w   = (const float*)d_in[14];

    float* out = (float*)d_out;
    float* logits = nullptr;
    if ((size_t)out_size >= (size_t)T_TOK * DDIM + (size_t)T_TOK * NEXP)
        logits = out + (size_t)T_TOK * DDIM;

    float* gbuf; cudaGetSymbolAddress((void**)&gbuf, g_gbuf);
    float* ubuf; cudaGetSymbolAddress((void**)&ubuf, g_ubuf);
    float* sgb;  cudaGetSymbolAddress((void**)&sgb,  g_sg);
    float* sub;  cudaGetSymbolAddress((void**)&sub,  g_su);

    zero_counts_kernel<<<1, 32>>>();
    router_kernel<<<T_TOK / 4, 128>>>(h, gate_w, sg_w, logits);

    // up projections (tf32 mma.sync)
    gemm_tc<0><<<dim3(FDIM / BN, CAP / BM, NEXP), 256>>>(h, w0, b0, gbuf);
    gemm_tc<0><<<dim3(FDIM / BN, CAP / BM, NEXP), 256>>>(h, w1, b1, ubuf);
    gemm_tc<1><<<dim3(FDIM / BN, T_TOK / BM, 1), 256>>>(h, sw0, sb0, sgb);
    gemm_tc<1><<<dim3(FDIM / BN, T_TOK / BM, 1), 256>>>(h, sw1, sb1, sub);

    // SwiGLU
    swiglu_routed_kernel<<<(unsigned)((size_t)NEXP * CAP * FDIM / 4 / 256), 256>>>();
    swiglu_shared_kernel<<<(unsigned)((size_t)T_TOK * FDIM / 4 / 256), 256>>>();

    // down projections: shared writes base, routed atomically accumulates
    gemm_tc<3><<<dim3(DDIM / BN, T_TOK / BM, 1), 256>>>(sgb, swo, sbo, out);
    gemm_tc<2><<<dim3(DDIM / BN, CAP / BM, NEXP), 256>>>(gbuf, wo, bo, out);
}

// round 5
// speedup vs baseline: 3.0065x; 1.1755x over previous
#include <cuda_runtime.h>
#include <math.h>
#include <stdint.h>

#define T_TOK 4096
#define DDIM  2048
#define NEXP  8
#define FDIM  512
#define CAP   4096
#define BM    128
#define BN    128
#define BK    16
#define SPAD  20     // smem row stride in words (BK + 4, conflict-free for compute LDS)

// ---------------------------------------------------------------------------
// Scratch (device globals; allocation is forbidden)
// ---------------------------------------------------------------------------
__device__ float g_gbuf[(size_t)NEXP * CAP * FDIM];  // routed: g, then silu(g)*u
__device__ float g_ubuf[(size_t)NEXP * CAP * FDIM];  // routed: u
__device__ float g_sg[(size_t)T_TOK * FDIM];         // shared: g, then silu(g)*u
__device__ float g_su[(size_t)T_TOK * FDIM];         // shared: u
__device__ int   g_cnt[NEXP];
__device__ int   g_tok[NEXP * CAP];
__device__ float g_wt[NEXP * CAP];
__device__ float g_gate[T_TOK];

__device__ __forceinline__ uint32_t tf32r(float f) {
    uint32_t r; asm("cvt.rna.tf32.f32 %0, %1;" : "=r"(r) : "f"(f)); return r;
}
__device__ __forceinline__ void mma8(float* d, const uint32_t* a, const uint32_t* b) {
    asm volatile(
        "mma.sync.aligned.m16n8k8.row.col.f32.tf32.tf32.f32 "
        "{%0,%1,%2,%3}, {%4,%5,%6,%7}, {%8,%9}, {%0,%1,%2,%3};"
        : "+f"(d[0]), "+f"(d[1]), "+f"(d[2]), "+f"(d[3])
        : "r"(a[0]), "r"(a[1]), "r"(a[2]), "r"(a[3]), "r"(b[0]), "r"(b[1]));
}

// ---------------------------------------------------------------------------
__global__ void zero_counts_kernel() {
    if (threadIdx.x < NEXP) g_cnt[threadIdx.x] = 0;
}

// ---------------------------------------------------------------------------
// Router: 1 warp per token. Full logits to out tail, top-2 (low-index ties),
// pairwise-softmax weights, per-expert token lists, shared sigmoid gate.
// ---------------------------------------------------------------------------
__global__ void router_kernel(const float* __restrict__ h,
                              const float* __restrict__ gate_w,
                              const float* __restrict__ sg_w,
                              float* __restrict__ logits_out) {
    int warp = threadIdx.x >> 5;
    int lane = threadIdx.x & 31;
    int t = blockIdx.x * 4 + warp;
    if (t >= T_TOK) return;

    float acc[9];
#pragma unroll
    for (int i = 0; i < 9; i++) acc[i] = 0.f;

    const float4* hp = (const float4*)(h + (size_t)t * DDIM);
    for (int d = lane; d < DDIM / 4; d += 32) {
        float4 hv = hp[d];
#pragma unroll
        for (int e = 0; e < NEXP; e++) {
            float4 w = ((const float4*)(gate_w + (size_t)e * DDIM))[d];
            acc[e] += hv.x * w.x + hv.y * w.y + hv.z * w.z + hv.w * w.w;
        }
        float4 w = ((const float4*)sg_w)[d];
        acc[8] += hv.x * w.x + hv.y * w.y + hv.z * w.z + hv.w * w.w;
    }
#pragma unroll
    for (int i = 0; i < 9; i++) {
#pragma unroll
        for (int off = 16; off > 0; off >>= 1)
            acc[i] += __shfl_down_sync(0xffffffffu, acc[i], off);
    }

    if (lane == 0) {
        if (logits_out) {
#pragma unroll
            for (int e = 0; e < NEXP; e++) logits_out[t * NEXP + e] = acc[e];
        }
        int i0 = 0;
#pragma unroll
        for (int e = 1; e < NEXP; e++) if (acc[e] > acc[i0]) i0 = e;
        int i1 = (i0 == 0) ? 1 : 0;
#pragma unroll
        for (int e = 0; e < NEXP; e++) if (e != i0 && e != i1 && acc[e] > acc[i1]) i1 = e;

        float wA = 1.f / (1.f + expf(acc[i1] - acc[i0]));
        float wB = 1.f - wA;

        int s0 = atomicAdd(&g_cnt[i0], 1);
        g_tok[i0 * CAP + s0] = t;  g_wt[i0 * CAP + s0] = wA;
        int s1 = atomicAdd(&g_cnt[i1], 1);
        g_tok[i1 * CAP + s1] = t;  g_wt[i1 * CAP + s1] = wB;

        g_gate[t] = 1.f / (1.f + expf(-acc[8]));
    }
}

// ---------------------------------------------------------------------------
// tf32 mma.sync GEMM: C[m,n] = sum_k A[m,k]*B[n,k] (+bias), 4 modes.
// CTA tile 128x128, 128 threads = 4 warps (2x2), warp tile 64x64.
// Register-prefetch pipeline: LDG for tile k+1 issued before compute on k.
// MODE 0: up-routed   A = h gathered; out[slot,f] = acc + b[e,f]
// MODE 1: up-shared   A = h direct;   out[t,f]    = acc + b[f]
// MODE 2: down-routed A = g_gbuf;     atomicAdd(out[tok,d], wt*(acc+bo[e,d]))
// MODE 3: down-shared A = g_sg;       out[t,d] = gate[t]*(acc+sbo[d])
// ---------------------------------------------------------------------------
template<int MODE>
__global__ void __launch_bounds__(128)
gemm_tc(const float* __restrict__ A, const float* __restrict__ B,
        const float* __restrict__ bias, float* __restrict__ out) {
    constexpr int K = (MODE < 2) ? DDIM : FDIM;
    const int e  = (MODE == 0 || MODE == 2) ? blockIdx.z : 0;
    const int Ne = (MODE == 0 || MODE == 2) ? g_cnt[e] : T_TOK;
    const int row0 = blockIdx.y * BM;
    if (row0 >= Ne) return;
    const int n0  = blockIdx.x * BN;
    const int tid  = threadIdx.x;
    const int lane = tid & 31;
    const int wid  = tid >> 5;
    const int wm   = (wid >> 1) * 64;   // warp m offset (2 rows of warps)
    const int wn   = (wid & 1) * 64;    // warp n offset (2 cols of warps)

    __shared__ uint32_t As[BM][SPAD];
    __shared__ uint32_t Bs[BN][SPAD];
    __shared__ int   sTok[BM];
    __shared__ float sWt[BM];

    if (MODE == 0 || MODE == 2) {
        int r = row0 + tid;
        int rr = (r < Ne) ? r : (Ne - 1);
        sTok[tid] = g_tok[e * CAP + rr];
        sWt[tid]  = g_wt[e * CAP + rr];
        __syncthreads();
    }

    const float* Bb = (MODE == 0) ? (B + (size_t)e * FDIM * DDIM)
                    : (MODE == 2) ? (B + (size_t)e * DDIM * FDIM)
                    : B;

    float acc[4][8][4];
#pragma unroll
    for (int i = 0; i < 4; i++)
#pragma unroll
        for (int j = 0; j < 8; j++)
#pragma unroll
            for (int r = 0; r < 4; r++) acc[i][j][r] = 0.f;

    // per-thread staging coords: 4 float4 per tile
    int rA[4], cA[4];
#pragma unroll
    for (int i = 0; i < 4; i++) {
        int idx = i * 128 + tid;
        rA[i] = idx >> 2;
        cA[i] = (idx & 3) * 4;
    }

    float4 pa[4], pb[4];
    // prologue: load tile kt=0
#pragma unroll
    for (int i = 0; i < 4; i++) {
        const float* ap;
        int r = rA[i];
        if (MODE == 0)      ap = A + (size_t)sTok[r] * DDIM + cA[i];
        else if (MODE == 1) ap = A + (size_t)(row0 + r) * DDIM + cA[i];
        else if (MODE == 2) ap = A + ((size_t)e * CAP + row0 + r) * FDIM + cA[i];
        else                ap = A + (size_t)(row0 + r) * FDIM + cA[i];
        pa[i] = *(const float4*)ap;
        pb[i] = *(const float4*)(Bb + (size_t)(n0 + r) * K + cA[i]);
    }

    for (int kt = 0; kt < K; kt += BK) {
        // ---- cvt + store staged tile ----
#pragma unroll
        for (int i = 0; i < 4; i++) {
            *(uint4*)&As[rA[i]][cA[i]] =
                make_uint4(tf32r(pa[i].x), tf32r(pa[i].y), tf32r(pa[i].z), tf32r(pa[i].w));
            *(uint4*)&Bs[rA[i]][cA[i]] =
                make_uint4(tf32r(pb[i].x), tf32r(pb[i].y), tf32r(pb[i].z), tf32r(pb[i].w));
        }
        __syncthreads();

        // ---- prefetch next tile (latency hidden by compute below) ----
        if (kt + BK < K) {
            int ktn = kt + BK;
#pragma unroll
            for (int i = 0; i < 4; i++) {
                const float* ap;
                int r = rA[i];
                if (MODE == 0)      ap = A + (size_t)sTok[r] * DDIM + ktn + cA[i];
                else if (MODE == 1) ap = A + (size_t)(row0 + r) * DDIM + ktn + cA[i];
                else if (MODE == 2) ap = A + ((size_t)e * CAP + row0 + r) * FDIM + ktn + cA[i];
                else                ap = A + (size_t)(row0 + r) * FDIM + ktn + cA[i];
                pa[i] = *(const float4*)ap;
                pb[i] = *(const float4*)(Bb + (size_t)(n0 + r) * K + ktn + cA[i]);
            }
        }

        // ---- compute: 2 k-steps of m16n8k8, warp tile 64x64 ----
        const int lr = lane >> 2, lc = lane & 3;
#pragma unroll
        for (int ks = 0; ks < BK; ks += 8) {
            uint32_t af[4][4], bf[8][2];
#pragma unroll
            for (int im = 0; im < 4; im++) {
                int rb = wm + im * 16 + lr;
                af[im][0] = As[rb][ks + lc];
                af[im][1] = As[rb + 8][ks + lc];
                af[im][2] = As[rb][ks + lc + 4];
                af[im][3] = As[rb + 8][ks + lc + 4];
            }
#pragma unroll
            for (int in = 0; in < 8; in++) {
                int nb = wn + in * 8 + lr;
                bf[in][0] = Bs[nb][ks + lc];
                bf[in][1] = Bs[nb][ks + lc + 4];
            }
#pragma unroll
            for (int im = 0; im < 4; im++)
#pragma unroll
                for (int in = 0; in < 8; in++)
                    mma8(acc[im][in], af[im], bf[in]);
        }
        __syncthreads();
    }

    // ---- epilogue ----
    const float* bp = (MODE == 0) ? (bias + e * FDIM)
                    : (MODE == 2) ? (bias + e * DDIM)
                    : bias;
#pragma unroll
    for (int im = 0; im < 4; im++) {
#pragma unroll
        for (int in = 0; in < 8; in++) {
#pragma unroll
            for (int rg = 0; rg < 4; rg++) {
                int r = wm + im * 16 + (lane >> 2) + ((rg & 2) ? 8 : 0);
                int c = wn + in * 8 + 2 * (lane & 3) + (rg & 1);
                if (row0 + r >= Ne) continue;
                float v = acc[im][in][rg];
                int col = n0 + c;
                if (MODE == 0) {
                    out[((size_t)e * CAP + row0 + r) * FDIM + col] = v + bp[col];
                } else if (MODE == 1) {
                    out[(size_t)(row0 + r) * FDIM + col] = v + bp[col];
                } else if (MODE == 2) {
                    int   t  = sTok[r];
                    float wt = sWt[r];
                    atomicAdd(out + (size_t)t * DDIM + col, wt * (v + bp[col]));
                } else {
                    out[(size_t)(row0 + r) * DDIM + col] =
                        g_gate[row0 + r] * (v + bp[col]);
                }
            }
        }
    }
}

// ---------------------------------------------------------------------------
// SwiGLU elementwise: buf_g = silu(buf_g) * buf_u (float4, valid rows only)
// ---------------------------------------------------------------------------
__global__ void swiglu_routed_kernel() {
    size_t i = (size_t)blockIdx.x * 256 + threadIdx.x;   // float4 index
    size_t row = i >> 7;                                  // FDIM/4 = 128 per row
    int e = (int)(row >> 12);                             // CAP = 4096 rows/expert
    int slot = (int)(row & (CAP - 1));
    if (slot >= g_cnt[e]) return;
    float4 g = ((float4*)g_gbuf)[i];
    float4 u = ((float4*)g_ubuf)[i];
    g.x = g.x / (1.f + expf(-g.x)) * u.x;
    g.y = g.y / (1.f + expf(-g.y)) * u.y;
    g.z = g.z / (1.f + expf(-g.z)) * u.z;
    g.w = g.w / (1.f + expf(-g.w)) * u.w;
    ((float4*)g_gbuf)[i] = g;
}

__global__ void swiglu_shared_kernel() {
    size_t i = (size_t)blockIdx.x * 256 + threadIdx.x;
    float4 g = ((float4*)g_sg)[i];
    float4 u = ((float4*)g_su)[i];
    g.x = g.x / (1.f + expf(-g.x)) * u.x;
    g.y = g.y / (1.f + expf(-g.y)) * u.y;
    g.z = g.z / (1.f + expf(-g.z)) * u.z;
    g.w = g.w / (1.f + expf(-g.w)) * u.w;
    ((float4*)g_sg)[i] = g;
}

// ---------------------------------------------------------------------------
extern "C" void kernel_launch(void* const* d_in, const int* in_sizes, int n_in,
                              void* d_out, int out_size) {
    const float* h      = (const float*)d_in[0];
    const float* gate_w = (const float*)d_in[1];
    const float* w0     = (const float*)d_in[2];
    const float* b0     = (const float*)d_in[3];
    const float* w1     = (const float*)d_in[4];
    const float* b1     = (const float*)d_in[5];
    const float* wo     = (const float*)d_in[6];
    const float* bo     = (const float*)d_in[7];
    const float* sw0    = (const float*)d_in[8];
    const float* sb0    = (const float*)d_in[9];
    const float* sw1    = (const float*)d_in[10];
    const float* sb1    = (const float*)d_in[11];
    const float* swo    = (const float*)d_in[12];
    const float* sbo    = (const float*)d_in[13];
    const float* sg_w   = (const float*)d_in[14];

    float* out = (float*)d_out;
    float* logits = nullptr;
    if ((size_t)out_size >= (size_t)T_TOK * DDIM + (size_t)T_TOK * NEXP)
        logits = out + (size_t)T_TOK * DDIM;

    float* gbuf; cudaGetSymbolAddress((void**)&gbuf, g_gbuf);
    float* ubuf; cudaGetSymbolAddress((void**)&ubuf, g_ubuf);
    float* sgb;  cudaGetSymbolAddress((void**)&sgb,  g_sg);
    float* sub;  cudaGetSymbolAddress((void**)&sub,  g_su);

    zero_counts_kernel<<<1, 32>>>();
    router_kernel<<<T_TOK / 4, 128>>>(h, gate_w, sg_w, logits);

    // up projections (tf32 mma.sync, 128-thread CTAs)
    gemm_tc<0><<<dim3(FDIM / BN, CAP / BM, NEXP), 128>>>(h, w0, b0, gbuf);
    gemm_tc<0><<<dim3(FDIM / BN, CAP / BM, NEXP), 128>>>(h, w1, b1, ubuf);
    gemm_tc<1><<<dim3(FDIM / BN, T_TOK / BM, 1), 128>>>(h, sw0, sb0, sgb);
    gemm_tc<1><<<dim3(FDIM / BN, T_TOK / BM, 1), 128>>>(h, sw1, sb1, sub);

    // SwiGLU
    swiglu_routed_kernel<<<(unsigned)((size_t)NEXP * CAP * FDIM / 4 / 256), 256>>>();
    swiglu_shared_kernel<<<(unsigned)((size_t)T_TOK * FDIM / 4 / 256), 256>>>();

    // down projections: shared writes base, routed atomically accumulates
    gemm_tc<3><<<dim3(DDIM / BN, T_TOK / BM, 1), 128>>>(sgb, swo, sbo, out);
    gemm_tc<2><<<dim3(DDIM / BN, CAP / BM, NEXP), 128>>>(gbuf, wo, bo, out);
}

// round 6
// speedup vs baseline: 3.0559x; 1.0164x over previous
#include <cuda_runtime.h>
#include <math.h>
#include <stdint.h>

#define T_TOK 4096
#define DDIM  2048
#define NEXP  8
#define FDIM  512
#define CAP   4096
#define BM    128
#define BN    128
#define BK    16
#define SPAD  20       // smem row stride in words (BK + 4): conflict-free, 16B-aligned rows
#define SBUF  (BM * SPAD * 4)   // one stage buffer in bytes = 10240

// ---------------------------------------------------------------------------
// Scratch (device globals; allocation is forbidden)
// ---------------------------------------------------------------------------
__device__ float g_h  [(size_t)T_TOK * DDIM];         // tf32-rounded h
__device__ float g_w0 [(size_t)NEXP * FDIM * DDIM];   // tf32-rounded weights
__device__ float g_w1 [(size_t)NEXP * FDIM * DDIM];
__device__ float g_wo [(size_t)NEXP * DDIM * FDIM];
__device__ float g_sw0[(size_t)FDIM * DDIM];
__device__ float g_sw1[(size_t)FDIM * DDIM];
__device__ float g_swo[(size_t)DDIM * FDIM];
__device__ float g_gbuf[(size_t)NEXP * CAP * FDIM];   // routed: g, then silu(g)*u (rounded)
__device__ float g_ubuf[(size_t)NEXP * CAP * FDIM];   // routed: u
__device__ float g_sg[(size_t)T_TOK * FDIM];          // shared: g, then silu(g)*u (rounded)
__device__ float g_su[(size_t)T_TOK * FDIM];          // shared: u
__device__ int   g_cnt[NEXP];
__device__ int   g_tok[NEXP * CAP];
__device__ float g_wt[NEXP * CAP];
__device__ float g_gate[T_TOK];

__device__ __forceinline__ uint32_t tf32r(float f) {
    uint32_t r; asm("cvt.rna.tf32.f32 %0, %1;" : "=r"(r) : "f"(f)); return r;
}
__device__ __forceinline__ float tf32f(float f) {
    return __uint_as_float(tf32r(f));
}
__device__ __forceinline__ uint32_t su32(const void* p) {
    uint32_t a;
    asm("{ .reg .u64 t; cvta.to.shared.u64 t, %1; cvt.u32.u64 %0, t; }" : "=r"(a) : "l"(p));
    return a;
}
__device__ __forceinline__ void cpasync16(uint32_t dst, const void* src) {
    asm volatile("cp.async.cg.shared.global [%0], [%1], 16;" :: "r"(dst), "l"(src) : "memory");
}
#define CP_COMMIT() asm volatile("cp.async.commit_group;" ::: "memory")
#define CP_WAIT(n)  asm volatile("cp.async.wait_group %0;" :: "n"(n) : "memory")

__device__ __forceinline__ void mma8(float* d, const uint32_t* a, const uint32_t* b) {
    asm volatile(
        "mma.sync.aligned.m16n8k8.row.col.f32.tf32.tf32.f32 "
        "{%0,%1,%2,%3}, {%4,%5,%6,%7}, {%8,%9}, {%0,%1,%2,%3};"
        : "+f"(d[0]), "+f"(d[1]), "+f"(d[2]), "+f"(d[3])
        : "r"(a[0]), "r"(a[1]), "r"(a[2]), "r"(a[3]), "r"(b[0]), "r"(b[1]));
}

// ---------------------------------------------------------------------------
__global__ void zero_counts_kernel() {
    if (threadIdx.x < NEXP) g_cnt[threadIdx.x] = 0;
}

// Elementwise tf32-RN rounding pass (float4 vectorized; n4 = n/4 multiple of 256)
__global__ void round_tf32_kernel(const float* __restrict__ in, float* __restrict__ out) {
    size_t i = (size_t)blockIdx.x * 256 + threadIdx.x;
    float4 v = ((const float4*)in)[i];
    v.x = tf32f(v.x); v.y = tf32f(v.y); v.z = tf32f(v.z); v.w = tf32f(v.w);
    ((float4*)out)[i] = v;
}

// ---------------------------------------------------------------------------
// Router: 1 warp per token. Full logits to out tail, top-2 (low-index ties),
// pairwise-softmax weights, per-expert token lists, shared sigmoid gate.
// ---------------------------------------------------------------------------
__global__ void router_kernel(const float* __restrict__ h,
                              const float* __restrict__ gate_w,
                              const float* __restrict__ sg_w,
                              float* __restrict__ logits_out) {
    int warp = threadIdx.x >> 5;
    int lane = threadIdx.x & 31;
    int t = blockIdx.x * 4 + warp;
    if (t >= T_TOK) return;

    float acc[9];
#pragma unroll
    for (int i = 0; i < 9; i++) acc[i] = 0.f;

    const float4* hp = (const float4*)(h + (size_t)t * DDIM);
    for (int d = lane; d < DDIM / 4; d += 32) {
        float4 hv = hp[d];
#pragma unroll
        for (int e = 0; e < NEXP; e++) {
            float4 w = ((const float4*)(gate_w + (size_t)e * DDIM))[d];
            acc[e] += hv.x * w.x + hv.y * w.y + hv.z * w.z + hv.w * w.w;
        }
        float4 w = ((const float4*)sg_w)[d];
        acc[8] += hv.x * w.x + hv.y * w.y + hv.z * w.z + hv.w * w.w;
    }
#pragma unroll
    for (int i = 0; i < 9; i++) {
#pragma unroll
        for (int off = 16; off > 0; off >>= 1)
            acc[i] += __shfl_down_sync(0xffffffffu, acc[i], off);
    }

    if (lane == 0) {
        if (logits_out) {
#pragma unroll
            for (int e = 0; e < NEXP; e++) logits_out[t * NEXP + e] = acc[e];
        }
        int i0 = 0;
#pragma unroll
        for (int e = 1; e < NEXP; e++) if (acc[e] > acc[i0]) i0 = e;
        int i1 = (i0 == 0) ? 1 : 0;
#pragma unroll
        for (int e = 0; e < NEXP; e++) if (e != i0 && e != i1 && acc[e] > acc[i1]) i1 = e;

        float wA = 1.f / (1.f + expf(acc[i1] - acc[i0]));
        float wB = 1.f - wA;

        int s0 = atomicAdd(&g_cnt[i0], 1);
        g_tok[i0 * CAP + s0] = t;  g_wt[i0 * CAP + s0] = wA;
        int s1 = atomicAdd(&g_cnt[i1], 1);
        g_tok[i1 * CAP + s1] = t;  g_wt[i1 * CAP + s1] = wB;

        g_gate[t] = 1.f / (1.f + expf(-acc[8]));
    }
}

// ---------------------------------------------------------------------------
// tf32 mma.sync GEMM over PRE-ROUNDED operands, cp.async 2-stage pipeline.
// CTA 128x128, 128 threads = 4 warps (2x2), warp tile 64x64, BK=16.
// MODE 0: up-routed   A = g_h gathered;  out[slot,f] = acc + b[e,f]
// MODE 1: up-shared   A = g_h direct;    out[t,f]    = acc + b[f]
// MODE 2: down-routed A = g_gbuf;        atomicAdd(out[tok,d], wt*(acc+bo[e,d]))
// MODE 3: down-shared A = g_sg;          out[t,d] = gate[t]*(acc+sbo[d])
// ---------------------------------------------------------------------------
template<int MODE>
__global__ void __launch_bounds__(128)
gemm_tc(const float* __restrict__ A, const float* __restrict__ B,
        const float* __restrict__ bias, float* __restrict__ out) {
    constexpr int K  = (MODE < 2) ? DDIM : FDIM;
    constexpr int NT = K / BK;
    const int e  = (MODE == 0 || MODE == 2) ? blockIdx.z : 0;
    const int Ne = (MODE == 0 || MODE == 2) ? g_cnt[e] : T_TOK;
    const int row0 = blockIdx.y * BM;
    if (row0 >= Ne) return;
    const int n0  = blockIdx.x * BN;
    const int tid  = threadIdx.x;
    const int lane = tid & 31;
    const int wid  = tid >> 5;
    const int wm   = (wid >> 1) * 64;
    const int wn   = (wid & 1) * 64;

    __shared__ uint32_t As[2][BM][SPAD];
    __shared__ uint32_t Bs[2][BN][SPAD];
    __shared__ int   sTok[BM];
    __shared__ float sWt[BM];

    if (MODE == 0 || MODE == 2) {
        int r = row0 + tid;
        int rr = (r < Ne) ? r : (Ne - 1);
        sTok[tid] = g_tok[e * CAP + rr];
        sWt[tid]  = g_wt[e * CAP + rr];
        __syncthreads();
    }

    const float* Bb = (MODE == 0) ? (B + (size_t)e * FDIM * DDIM)
                    : (MODE == 2) ? (B + (size_t)e * DDIM * FDIM)
                    : B;

    float acc[4][8][4];
#pragma unroll
    for (int i = 0; i < 4; i++)
#pragma unroll
        for (int j = 0; j < 8; j++)
#pragma unroll
            for (int r = 0; r < 4; r++) acc[i][j][r] = 0.f;

    // per-thread staging: 4 x 16B chunks per tile per matrix
    const float* aptr[4];
    const float* bptr[4];
    uint32_t     dA[4], dB[4];
#pragma unroll
    for (int i = 0; i < 4; i++) {
        int idx = i * 128 + tid;
        int r  = idx >> 2;
        int c4 = (idx & 3) * 4;
        const float* ap;
        if (MODE == 0)      ap = A + (size_t)sTok[r] * DDIM + c4;
        else if (MODE == 1) ap = A + (size_t)(row0 + r) * DDIM + c4;
        else if (MODE == 2) ap = A + ((size_t)e * CAP + row0 + r) * FDIM + c4;
        else                ap = A + (size_t)(row0 + r) * FDIM + c4;
        aptr[i] = ap;
        bptr[i] = Bb + (size_t)(n0 + r) * K + c4;
        dA[i] = su32(&As[0][r][c4]);
        dB[i] = su32(&Bs[0][r][c4]);
    }

    // prologue: stage tile 0 into buf 0
#pragma unroll
    for (int i = 0; i < 4; i++) {
        cpasync16(dA[i], aptr[i]);
        cpasync16(dB[i], bptr[i]);
    }
    CP_COMMIT();

    for (int it = 0; it < NT; it++) {
        const int buf = it & 1;
        if (it + 1 < NT) {
            const int nbuf = (it + 1) & 1;
            const int koff = (it + 1) * BK;
#pragma unroll
            for (int i = 0; i < 4; i++) {
                cpasync16(dA[i] + nbuf * SBUF, aptr[i] + koff);
                cpasync16(dB[i] + nbuf * SBUF, bptr[i] + koff);
            }
            CP_COMMIT();
            CP_WAIT(1);
        } else {
            CP_WAIT(0);
        }
        __syncthreads();

        const int lr = lane >> 2, lc = lane & 3;
#pragma unroll
        for (int ks = 0; ks < BK; ks += 8) {
            uint32_t af[4][4], bf[8][2];
#pragma unroll
            for (int im = 0; im < 4; im++) {
                int rb = wm + im * 16 + lr;
                af[im][0] = As[buf][rb][ks + lc];
                af[im][1] = As[buf][rb + 8][ks + lc];
                af[im][2] = As[buf][rb][ks + lc + 4];
                af[im][3] = As[buf][rb + 8][ks + lc + 4];
            }
#pragma unroll
            for (int in = 0; in < 8; in++) {
                int nb = wn + in * 8 + lr;
                bf[in][0] = Bs[buf][nb][ks + lc];
                bf[in][1] = Bs[buf][nb][ks + lc + 4];
            }
#pragma unroll
            for (int im = 0; im < 4; im++)
#pragma unroll
                for (int in = 0; in < 8; in++)
                    mma8(acc[im][in], af[im], bf[in]);
        }
        __syncthreads();
    }

    // ---- epilogue ----
    const float* bp = (MODE == 0) ? (bias + e * FDIM)
                    : (MODE == 2) ? (bias + e * DDIM)
                    : bias;
#pragma unroll
    for (int im = 0; im < 4; im++) {
#pragma unroll
        for (int in = 0; in < 8; in++) {
#pragma unroll
            for (int rg = 0; rg < 4; rg++) {
                int r = wm + im * 16 + (lane >> 2) + ((rg & 2) ? 8 : 0);
                int c = wn + in * 8 + 2 * (lane & 3) + (rg & 1);
                if (row0 + r >= Ne) continue;
                float v = acc[im][in][rg];
                int col = n0 + c;
                if (MODE == 0) {
                    out[((size_t)e * CAP + row0 + r) * FDIM + col] = v + bp[col];
                } else if (MODE == 1) {
                    out[(size_t)(row0 + r) * FDIM + col] = v + bp[col];
                } else if (MODE == 2) {
                    int   t  = sTok[r];
                    float wt = sWt[r];
                    atomicAdd(out + (size_t)t * DDIM + col, wt * (v + bp[col]));
                } else {
                    out[(size_t)(row0 + r) * DDIM + col] =
                        g_gate[row0 + r] * (v + bp[col]);
                }
            }
        }
    }
}

// ---------------------------------------------------------------------------
// SwiGLU elementwise: buf_g = tf32(silu(buf_g) * buf_u)  (float4)
// ---------------------------------------------------------------------------
__global__ void swiglu_routed_kernel() {
    size_t i = (size_t)blockIdx.x * 256 + threadIdx.x;   // float4 index
    size_t row = i >> 7;                                  // FDIM/4 = 128 per row
    int e = (int)(row >> 12);                             // CAP = 4096 rows/expert
    int slot = (int)(row & (CAP - 1));
    if (slot >= g_cnt[e]) return;
    float4 g = ((float4*)g_gbuf)[i];
    float4 u = ((float4*)g_ubuf)[i];
    g.x = tf32f(g.x / (1.f + expf(-g.x)) * u.x);
    g.y = tf32f(g.y / (1.f + expf(-g.y)) * u.y);
    g.z = tf32f(g.z / (1.f + expf(-g.z)) * u.z);
    g.w = tf32f(g.w / (1.f + expf(-g.w)) * u.w);
    ((float4*)g_gbuf)[i] = g;
}

__global__ void swiglu_shared_kernel() {
    size_t i = (size_t)blockIdx.x * 256 + threadIdx.x;
    float4 g = ((float4*)g_sg)[i];
    float4 u = ((float4*)g_su)[i];
    g.x = tf32f(g.x / (1.f + expf(-g.x)) * u.x);
    g.y = tf32f(g.y / (1.f + expf(-g.y)) * u.y);
    g.z = tf32f(g.z / (1.f + expf(-g.z)) * u.z);
    g.w = tf32f(g.w / (1.f + expf(-g.w)) * u.w);
    ((float4*)g_sg)[i] = g;
}

// ---------------------------------------------------------------------------
extern "C" void kernel_launch(void* const* d_in, const int* in_sizes, int n_in,
                              void* d_out, int out_size) {
    const float* h      = (const float*)d_in[0];
    const float* gate_w = (const float*)d_in[1];
    const float* w0     = (const float*)d_in[2];
    const float* b0     = (const float*)d_in[3];
    const float* w1     = (const float*)d_in[4];
    const float* b1     = (const float*)d_in[5];
    const float* wo     = (const float*)d_in[6];
    const float* bo     = (const float*)d_in[7];
    const float* sw0    = (const float*)d_in[8];
    const float* sb0    = (const float*)d_in[9];
    const float* sw1    = (const float*)d_in[10];
    const float* sb1    = (const float*)d_in[11];
    const float* swo    = (const float*)d_in[12];
    const float* sbo    = (const float*)d_in[13];
    const float* sg_w   = (const float*)d_in[14];

    float* out = (float*)d_out;
    float* logits = nullptr;
    if ((size_t)out_size >= (size_t)T_TOK * DDIM + (size_t)T_TOK * NEXP)
        logits = out + (size_t)T_TOK * DDIM;

    float *gh, *gw0, *gw1, *gwo, *gsw0, *gsw1, *gswo, *gbuf, *ubuf, *sgb, *sub;
    cudaGetSymbolAddress((void**)&gh,   g_h);
    cudaGetSymbolAddress((void**)&gw0,  g_w0);
    cudaGetSymbolAddress((void**)&gw1,  g_w1);
    cudaGetSymbolAddress((void**)&gwo,  g_wo);
    cudaGetSymbolAddress((void**)&gsw0, g_sw0);
    cudaGetSymbolAddress((void**)&gsw1, g_sw1);
    cudaGetSymbolAddress((void**)&gswo, g_swo);
    cudaGetSymbolAddress((void**)&gbuf, g_gbuf);
    cudaGetSymbolAddress((void**)&ubuf, g_ubuf);
    cudaGetSymbolAddress((void**)&sgb,  g_sg);
    cudaGetSymbolAddress((void**)&sub,  g_su);

    zero_counts_kernel<<<1, 32>>>();
    router_kernel<<<T_TOK / 4, 128>>>(h, gate_w, sg_w, logits);

    // tf32-RN pre-rounding passes (bandwidth-bound)
    const unsigned NB_BIG = (unsigned)((size_t)T_TOK * DDIM / 4 / 256);      // 8192
    const unsigned NB_W   = (unsigned)((size_t)NEXP * FDIM * DDIM / 4 / 256);
    const unsigned NB_S   = (unsigned)((size_t)FDIM * DDIM / 4 / 256);
    round_tf32_kernel<<<NB_BIG, 256>>>(h,   gh);
    round_tf32_kernel<<<NB_W,   256>>>(w0,  gw0);
    round_tf32_kernel<<<NB_W,   256>>>(w1,  gw1);
    round_tf32_kernel<<<NB_W,   256>>>(wo,  gwo);
    round_tf32_kernel<<<NB_S,   256>>>(sw0, gsw0);
    round_tf32_kernel<<<NB_S,   256>>>(sw1, gsw1);
    round_tf32_kernel<<<NB_S,   256>>>(swo, gswo);

    // up projections
    gemm_tc<0><<<dim3(FDIM / BN, CAP / BM, NEXP), 128>>>(gh, gw0, b0, gbuf);
    gemm_tc<0><<<dim3(FDIM / BN, CAP / BM, NEXP), 128>>>(gh, gw1, b1, ubuf);
    gemm_tc<1><<<dim3(FDIM / BN, T_TOK / BM, 1), 128>>>(gh, gsw0, sb0, sgb);
    gemm_tc<1><<<dim3(FDIM / BN, T_TOK / BM, 1), 128>>>(gh, gsw1, sb1, sub);

    // SwiGLU (outputs tf32-rounded for the down GEMMs)
    swiglu_routed_kernel<<<(unsigned)((size_t)NEXP * CAP * FDIM / 4 / 256), 256>>>();
    swiglu_shared_kernel<<<(unsigned)((size_t)T_TOK * FDIM / 4 / 256), 256>>>();

    // down projections: shared writes base, routed atomically accumulates
    gemm_tc<3><<<dim3(DDIM / BN, T_TOK / BM, 1), 128>>>(sgb, gswo, sbo, out);
    gemm_tc<2><<<dim3(DDIM / BN, CAP / BM, NEXP), 128>>>(gbuf, gwo, bo, out);
}

// round 7
// speedup vs baseline: 5.1990x; 1.7013x over previous
#include <cuda_runtime.h>
#include <cuda_fp16.h>
#include <math.h>
#include <stdint.h>

#define T_TOK 4096
#define DDIM  2048
#define NEXP  8
#define FDIM  512
#define CAP   4096
#define BM    128
#define BN    128
#define BKH   32        // K-chunk in halves (= 64 bytes per row)
#define SPAD  20        // smem row stride in uint32 (16 data + 4 pad; 80B, 16B-aligned)
#define SBUF  (BM * SPAD * 4)   // one stage buffer bytes = 10240

// ---------------------------------------------------------------------------
// Scratch (device globals; allocation is forbidden)
// ---------------------------------------------------------------------------
__device__ __half g_h16 [(size_t)T_TOK * DDIM];
__device__ __half g_w0h [(size_t)NEXP * FDIM * DDIM];
__device__ __half g_w1h [(size_t)NEXP * FDIM * DDIM];
__device__ __half g_woh [(size_t)NEXP * DDIM * FDIM];
__device__ __half g_sw0h[(size_t)FDIM * DDIM];
__device__ __half g_sw1h[(size_t)FDIM * DDIM];
__device__ __half g_swoh[(size_t)DDIM * FDIM];
__device__ float  g_gbuf[(size_t)NEXP * CAP * FDIM];   // routed g (fp32)
__device__ float  g_ubuf[(size_t)NEXP * CAP * FDIM];   // routed u (fp32)
__device__ __half g_ih  [(size_t)NEXP * CAP * FDIM];   // routed silu(g)*u (fp16)
__device__ float  g_sg  [(size_t)T_TOK * FDIM];        // shared g (fp32)
__device__ float  g_su  [(size_t)T_TOK * FDIM];        // shared u (fp32)
__device__ __half g_sih [(size_t)T_TOK * FDIM];        // shared silu(g)*u (fp16)
__device__ int    g_cnt[NEXP];
__device__ int    g_tok[NEXP * CAP];
__device__ float  g_wt[NEXP * CAP];
__device__ float  g_gate[T_TOK];

__device__ __forceinline__ uint32_t su32(const void* p) {
    uint32_t a;
    asm("{ .reg .u64 t; cvta.to.shared.u64 t, %1; cvt.u32.u64 %0, t; }" : "=r"(a) : "l"(p));
    return a;
}
__device__ __forceinline__ void cpasync16(uint32_t dst, const void* src) {
    asm volatile("cp.async.cg.shared.global [%0], [%1], 16;" :: "r"(dst), "l"(src) : "memory");
}
#define CP_COMMIT() asm volatile("cp.async.commit_group;" ::: "memory")
#define CP_WAIT(n)  asm volatile("cp.async.wait_group %0;" :: "n"(n) : "memory")

__device__ __forceinline__ void mma16(float* d, const uint32_t* a, const uint32_t* b) {
    asm volatile(
        "mma.sync.aligned.m16n8k16.row.col.f32.f16.f16.f32 "
        "{%0,%1,%2,%3}, {%4,%5,%6,%7}, {%8,%9}, {%0,%1,%2,%3};"
        : "+f"(d[0]), "+f"(d[1]), "+f"(d[2]), "+f"(d[3])
        : "r"(a[0]), "r"(a[1]), "r"(a[2]), "r"(a[3]), "r"(b[0]), "r"(b[1]));
}

// ---------------------------------------------------------------------------
__global__ void zero_counts_kernel() {
    if (threadIdx.x < NEXP) g_cnt[threadIdx.x] = 0;
}

// fp32 -> fp16 conversion (RN), float4-vectorized
__global__ void cvt_half_kernel(const float* __restrict__ in, __half* __restrict__ out) {
    size_t i = (size_t)blockIdx.x * 256 + threadIdx.x;   // float4 index
    float4 v = ((const float4*)in)[i];
    __half2 lo = __floats2half2_rn(v.x, v.y);
    __half2 hi = __floats2half2_rn(v.z, v.w);
    ((__half2*)out)[i * 2]     = lo;
    ((__half2*)out)[i * 2 + 1] = hi;
}

// ---------------------------------------------------------------------------
// Router (fp32): 1 warp per token. Full logits, top-2 (low-index ties),
// pairwise-softmax weights, per-expert token lists, shared sigmoid gate.
// ---------------------------------------------------------------------------
__global__ void router_kernel(const float* __restrict__ h,
                              const float* __restrict__ gate_w,
                              const float* __restrict__ sg_w,
                              float* __restrict__ logits_out) {
    int warp = threadIdx.x >> 5;
    int lane = threadIdx.x & 31;
    int t = blockIdx.x * 4 + warp;
    if (t >= T_TOK) return;

    float acc[9];
#pragma unroll
    for (int i = 0; i < 9; i++) acc[i] = 0.f;

    const float4* hp = (const float4*)(h + (size_t)t * DDIM);
    for (int d = lane; d < DDIM / 4; d += 32) {
        float4 hv = hp[d];
#pragma unroll
        for (int e = 0; e < NEXP; e++) {
            float4 w = ((const float4*)(gate_w + (size_t)e * DDIM))[d];
            acc[e] += hv.x * w.x + hv.y * w.y + hv.z * w.z + hv.w * w.w;
        }
        float4 w = ((const float4*)sg_w)[d];
        acc[8] += hv.x * w.x + hv.y * w.y + hv.z * w.z + hv.w * w.w;
    }
#pragma unroll
    for (int i = 0; i < 9; i++) {
#pragma unroll
        for (int off = 16; off > 0; off >>= 1)
            acc[i] += __shfl_down_sync(0xffffffffu, acc[i], off);
    }

    if (lane == 0) {
        if (logits_out) {
#pragma unroll
            for (int e = 0; e < NEXP; e++) logits_out[t * NEXP + e] = acc[e];
        }
        int i0 = 0;
#pragma unroll
        for (int e = 1; e < NEXP; e++) if (acc[e] > acc[i0]) i0 = e;
        int i1 = (i0 == 0) ? 1 : 0;
#pragma unroll
        for (int e = 0; e < NEXP; e++) if (e != i0 && e != i1 && acc[e] > acc[i1]) i1 = e;

        float wA = 1.f / (1.f + expf(acc[i1] - acc[i0]));
        float wB = 1.f - wA;

        int s0 = atomicAdd(&g_cnt[i0], 1);
        g_tok[i0 * CAP + s0] = t;  g_wt[i0 * CAP + s0] = wA;
        int s1 = atomicAdd(&g_cnt[i1], 1);
        g_tok[i1 * CAP + s1] = t;  g_wt[i1 * CAP + s1] = wB;

        g_gate[t] = 1.f / (1.f + expf(-acc[8]));
    }
}

// ---------------------------------------------------------------------------
// fp16 mma.sync GEMM (m16n8k16) over pre-converted operands, cp.async 2-stage.
// CTA 128x128, 256 threads = 8 warps (2 rows x 4 cols), warp tile 64x32.
// BKH=32 halves per ktile (2 k-steps of 16). fp32 accumulate + fp32 bias.
// MODE 0: up-routed   A = g_h16 gathered;  out[slot,f] = acc + b[e,f]
// MODE 1: up-shared   A = g_h16 direct;    out[t,f]    = acc + b[f]
// MODE 2: down-routed A = g_ih;            atomicAdd(out[tok,d], wt*(acc+bo[e,d]))
// MODE 3: down-shared A = g_sih;           out[t,d] = gate[t]*(acc+sbo[d])
// ---------------------------------------------------------------------------
template<int MODE>
__global__ void __launch_bounds__(256, 2)
gemm_h(const __half* __restrict__ A, const __half* __restrict__ B,
       const float* __restrict__ bias, float* __restrict__ out) {
    constexpr int K  = (MODE < 2) ? DDIM : FDIM;   // in halves (elements)
    constexpr int NT = K / BKH;
    const int e  = (MODE == 0 || MODE == 2) ? blockIdx.z : 0;
    const int Ne = (MODE == 0 || MODE == 2) ? g_cnt[e] : T_TOK;
    const int row0 = blockIdx.y * BM;
    if (row0 >= Ne) return;
    const int n0  = blockIdx.x * BN;
    const int tid  = threadIdx.x;
    const int lane = tid & 31;
    const int wid  = tid >> 5;
    const int wm   = (wid >> 2) * 64;   // 2 warp-rows
    const int wn   = (wid & 3) * 32;    // 4 warp-cols

    __shared__ uint32_t As[2][BM][SPAD];
    __shared__ uint32_t Bs[2][BN][SPAD];
    __shared__ int   sTok[BM];
    __shared__ float sWt[BM];

    if (MODE == 0 || MODE == 2) {
        if (tid < BM) {
            int r = row0 + tid;
            int rr = (r < Ne) ? r : (Ne - 1);
            sTok[tid] = g_tok[e * CAP + rr];
            sWt[tid]  = g_wt[e * CAP + rr];
        }
        __syncthreads();
    }

    const __half* Bb = (MODE == 0) ? (B + (size_t)e * FDIM * DDIM)
                     : (MODE == 2) ? (B + (size_t)e * DDIM * FDIM)
                     : B;

    float acc[4][4][4];
#pragma unroll
    for (int i = 0; i < 4; i++)
#pragma unroll
        for (int j = 0; j < 4; j++)
#pragma unroll
            for (int r = 0; r < 4; r++) acc[i][j][r] = 0.f;

    // staging: tile = 128 rows x 64B = 512 x 16B chunks; 2 per thread per matrix
    const __half* aptr[2];
    const __half* bptr[2];
    uint32_t      dA[2], dB[2];
#pragma unroll
    for (int i = 0; i < 2; i++) {
        int idx = i * 256 + tid;
        int r  = idx >> 2;            // row 0..127
        int ch = (idx & 3) * 8;       // half offset within row (8 halves = 16B)
        const __half* ap;
        if (MODE == 0)      ap = A + (size_t)sTok[r] * DDIM + ch;
        else if (MODE == 1) ap = A + (size_t)(row0 + r) * DDIM + ch;
        else if (MODE == 2) ap = A + ((size_t)e * CAP + row0 + r) * FDIM + ch;
        else                ap = A + (size_t)(row0 + r) * FDIM + ch;
        aptr[i] = ap;
        bptr[i] = Bb + (size_t)(n0 + r) * K + ch;
        dA[i] = su32(&As[0][r][(idx & 3) * 4]);
        dB[i] = su32(&Bs[0][r][(idx & 3) * 4]);
    }

    // prologue: stage tile 0 into buf 0
#pragma unroll
    for (int i = 0; i < 2; i++) {
        cpasync16(dA[i], aptr[i]);
        cpasync16(dB[i], bptr[i]);
    }
    CP_COMMIT();

    for (int it = 0; it < NT; it++) {
        const int buf = it & 1;
        if (it + 1 < NT) {
            const int nbuf = (it + 1) & 1;
            const int koff = (it + 1) * BKH;
#pragma unroll
            for (int i = 0; i < 2; i++) {
                cpasync16(dA[i] + nbuf * SBUF, aptr[i] + koff);
                cpasync16(dB[i] + nbuf * SBUF, bptr[i] + koff);
            }
            CP_COMMIT();
            CP_WAIT(1);
        } else {
            CP_WAIT(0);
        }
        __syncthreads();

        const int lr = lane >> 2, lc = lane & 3;
#pragma unroll
        for (int ks = 0; ks < 2; ks++) {
            const int base = ks * 8;
            uint32_t af[4][4], bf[4][2];
#pragma unroll
            for (int im = 0; im < 4; im++) {
                int rb = wm + im * 16 + lr;
                af[im][0] = As[buf][rb][base + lc];
                af[im][1] = As[buf][rb + 8][base + lc];
                af[im][2] = As[buf][rb][base + lc + 4];
                af[im][3] = As[buf][rb + 8][base + lc + 4];
            }
#pragma unroll
            for (int in = 0; in < 4; in++) {
                int nb = wn + in * 8 + lr;
                bf[in][0] = Bs[buf][nb][base + lc];
                bf[in][1] = Bs[buf][nb][base + lc + 4];
            }
#pragma unroll
            for (int im = 0; im < 4; im++)
#pragma unroll
                for (int in = 0; in < 4; in++)
                    mma16(acc[im][in], af[im], bf[in]);
        }
        __syncthreads();
    }

    // ---- epilogue (fp32 bias, fp32 outputs) ----
    const float* bp = (MODE == 0) ? (bias + e * FDIM)
                    : (MODE == 2) ? (bias + e * DDIM)
                    : bias;
#pragma unroll
    for (int im = 0; im < 4; im++) {
#pragma unroll
        for (int in = 0; in < 4; in++) {
#pragma unroll
            for (int rg = 0; rg < 4; rg++) {
                int r = wm + im * 16 + (lane >> 2) + ((rg & 2) ? 8 : 0);
                int c = wn + in * 8 + 2 * (lane & 3) + (rg & 1);
                if (row0 + r >= Ne) continue;
                float v = acc[im][in][rg];
                int col = n0 + c;
                if (MODE == 0) {
                    out[((size_t)e * CAP + row0 + r) * FDIM + col] = v + bp[col];
                } else if (MODE == 1) {
                    out[(size_t)(row0 + r) * FDIM + col] = v + bp[col];
                } else if (MODE == 2) {
                    int   t  = sTok[r];
                    float wt = sWt[r];
                    atomicAdd(out + (size_t)t * DDIM + col, wt * (v + bp[col]));
                } else {
                    out[(size_t)(row0 + r) * DDIM + col] =
                        g_gate[row0 + r] * (v + bp[col]);
                }
            }
        }
    }
}

// ---------------------------------------------------------------------------
// SwiGLU elementwise in fp32, emit fp16 for the down GEMMs
// ---------------------------------------------------------------------------
__global__ void swiglu_routed_kernel() {
    size_t i = (size_t)blockIdx.x * 256 + threadIdx.x;   // float4 index
    size_t row = i >> 7;                                  // FDIM/4 = 128 per row
    int e = (int)(row >> 12);                             // CAP rows per expert
    int slot = (int)(row & (CAP - 1));
    if (slot >= g_cnt[e]) return;
    float4 g = ((float4*)g_gbuf)[i];
    float4 u = ((float4*)g_ubuf)[i];
    float r0 = g.x / (1.f + expf(-g.x)) * u.x;
    float r1 = g.y / (1.f + expf(-g.y)) * u.y;
    float r2 = g.z / (1.f + expf(-g.z)) * u.z;
    float r3 = g.w / (1.f + expf(-g.w)) * u.w;
    ((__half2*)g_ih)[i * 2]     = __floats2half2_rn(r0, r1);
    ((__half2*)g_ih)[i * 2 + 1] = __floats2half2_rn(r2, r3);
}

__global__ void swiglu_shared_kernel() {
    size_t i = (size_t)blockIdx.x * 256 + threadIdx.x;
    float4 g = ((float4*)g_sg)[i];
    float4 u = ((float4*)g_su)[i];
    float r0 = g.x / (1.f + expf(-g.x)) * u.x;
    float r1 = g.y / (1.f + expf(-g.y)) * u.y;
    float r2 = g.z / (1.f + expf(-g.z)) * u.z;
    float r3 = g.w / (1.f + expf(-g.w)) * u.w;
    ((__half2*)g_sih)[i * 2]     = __floats2half2_rn(r0, r1);
    ((__half2*)g_sih)[i * 2 + 1] = __floats2half2_rn(r2, r3);
}

// ---------------------------------------------------------------------------
extern "C" void kernel_launch(void* const* d_in, const int* in_sizes, int n_in,
                              void* d_out, int out_size) {
    const float* h      = (const float*)d_in[0];
    const float* gate_w = (const float*)d_in[1];
    const float* w0     = (const float*)d_in[2];
    const float* b0     = (const float*)d_in[3];
    const float* w1     = (const float*)d_in[4];
    const float* b1     = (const float*)d_in[5];
    const float* wo     = (const float*)d_in[6];
    const float* bo     = (const float*)d_in[7];
    const float* sw0    = (const float*)d_in[8];
    const float* sb0    = (const float*)d_in[9];
    const float* sw1    = (const float*)d_in[10];
    const float* sb1    = (const float*)d_in[11];
    const float* swo    = (const float*)d_in[12];
    const float* sbo    = (const float*)d_in[13];
    const float* sg_w   = (const float*)d_in[14];

    float* out = (float*)d_out;
    float* logits = nullptr;
    if ((size_t)out_size >= (size_t)T_TOK * DDIM + (size_t)T_TOK * NEXP)
        logits = out + (size_t)T_TOK * DDIM;

    __half *h16, *w0h, *w1h, *woh, *sw0h, *sw1h, *swoh, *ih, *sih;
    float *gbuf, *ubuf, *sgb, *sub;
    cudaGetSymbolAddress((void**)&h16,  g_h16);
    cudaGetSymbolAddress((void**)&w0h,  g_w0h);
    cudaGetSymbolAddress((void**)&w1h,  g_w1h);
    cudaGetSymbolAddress((void**)&woh,  g_woh);
    cudaGetSymbolAddress((void**)&sw0h, g_sw0h);
    cudaGetSymbolAddress((void**)&sw1h, g_sw1h);
    cudaGetSymbolAddress((void**)&swoh, g_swoh);
    cudaGetSymbolAddress((void**)&ih,   g_ih);
    cudaGetSymbolAddress((void**)&sih,  g_sih);
    cudaGetSymbolAddress((void**)&gbuf, g_gbuf);
    cudaGetSymbolAddress((void**)&ubuf, g_ubuf);
    cudaGetSymbolAddress((void**)&sgb,  g_sg);
    cudaGetSymbolAddress((void**)&sub,  g_su);

    zero_counts_kernel<<<1, 32>>>();
    router_kernel<<<T_TOK / 4, 128>>>(h, gate_w, sg_w, logits);

    // fp32 -> fp16 operand conversion (bandwidth-bound)
    const unsigned NB_H = (unsigned)((size_t)T_TOK * DDIM / 4 / 256);
    const unsigned NB_W = (unsigned)((size_t)NEXP * FDIM * DDIM / 4 / 256);
    const unsigned NB_S = (unsigned)((size_t)FDIM * DDIM / 4 / 256);
    cvt_half_kernel<<<NB_H, 256>>>(h,   h16);
    cvt_half_kernel<<<NB_W, 256>>>(w0,  w0h);
    cvt_half_kernel<<<NB_W, 256>>>(w1,  w1h);
    cvt_half_kernel<<<NB_W, 256>>>(wo,  woh);
    cvt_half_kernel<<<NB_S, 256>>>(sw0, sw0h);
    cvt_half_kernel<<<NB_S, 256>>>(sw1, sw1h);
    cvt_half_kernel<<<NB_S, 256>>>(swo, swoh);

    // up projections (fp16 mma.sync, fp32 accumulate)
    gemm_h<0><<<dim3(FDIM / BN, CAP / BM, NEXP), 256>>>(h16, w0h, b0, gbuf);
    gemm_h<0><<<dim3(FDIM / BN, CAP / BM, NEXP), 256>>>(h16, w1h, b1, ubuf);
    gemm_h<1><<<dim3(FDIM / BN, T_TOK / BM, 1), 256>>>(h16, sw0h, sb0, sgb);
    gemm_h<1><<<dim3(FDIM / BN, T_TOK / BM, 1), 256>>>(h16, sw1h, sb1, sub);

    // SwiGLU (fp32 math, fp16 outputs)
    swiglu_routed_kernel<<<(unsigned)((size_t)NEXP * CAP * FDIM / 4 / 256), 256>>>();
    swiglu_shared_kernel<<<(unsigned)((size_t)T_TOK * FDIM / 4 / 256), 256>>>();

    // down projections: shared writes base, routed atomically accumulates
    gemm_h<3><<<dim3(DDIM / BN, T_TOK / BM, 1), 256>>>(sih, swoh, sbo, out);
    gemm_h<2><<<dim3(DDIM / BN, CAP / BM, NEXP), 256>>>(ih, woh, bo, out);
}

// round 10
// speedup vs baseline: 5.3277x; 1.0248x over previous
#include <cuda_runtime.h>
#include <cuda_fp16.h>
#include <math.h>
#include <stdint.h>

#define T_TOK 4096
#define DDIM  2048
#define NEXP  8
#define FDIM  512
#define CAP   4096
#define BM    128
#define BN    128
#define BKH   32        // K-chunk in halves (= 64 bytes per row)
#define SPAD  20        // smem row stride in uint32 (16 data + 4 pad)
#define SBUF  (BM * SPAD * 4)   // one stage buffer bytes = 10240

// ---------------------------------------------------------------------------
// Scratch (device globals; allocation is forbidden)
// ---------------------------------------------------------------------------
__device__ __half g_h16 [(size_t)T_TOK * DDIM];
__device__ __half g_w0h [(size_t)NEXP * FDIM * DDIM];
__device__ __half g_w1h [(size_t)NEXP * FDIM * DDIM];
__device__ __half g_woh [(size_t)NEXP * DDIM * FDIM];
__device__ __half g_sw0h[(size_t)FDIM * DDIM];
__device__ __half g_sw1h[(size_t)FDIM * DDIM];
__device__ __half g_swoh[(size_t)DDIM * FDIM];
__device__ __half g_gh  [(size_t)NEXP * CAP * FDIM];   // routed g   (producer: MODE 0)
__device__ __half g_ih  [(size_t)NEXP * CAP * FDIM];   // routed silu(g)*u (producer: MODE 4)
__device__ __half g_sgh [(size_t)T_TOK * FDIM];        // shared g   (producer: MODE 1)
__device__ __half g_sih [(size_t)T_TOK * FDIM];        // shared silu(g)*u (producer: MODE 5)
__device__ int    g_cnt[NEXP];
__device__ int    g_tok[NEXP * CAP];
__device__ float  g_wt[NEXP * CAP];
__device__ float  g_gate[T_TOK];

__device__ __forceinline__ uint32_t su32(const void* p) {
    uint32_t a;
    asm("{ .reg .u64 t; cvta.to.shared.u64 t, %1; cvt.u32.u64 %0, t; }" : "=r"(a) : "l"(p));
    return a;
}
__device__ __forceinline__ void cpasync16(uint32_t dst, const void* src) {
    asm volatile("cp.async.cg.shared.global [%0], [%1], 16;" :: "r"(dst), "l"(src) : "memory");
}
#define CP_COMMIT() asm volatile("cp.async.commit_group;" ::: "memory")
#define CP_WAIT(n)  asm volatile("cp.async.wait_group %0;" :: "n"(n) : "memory")

__device__ __forceinline__ void mma16(float* d, const uint32_t* a, const uint32_t* b) {
    asm volatile(
        "mma.sync.aligned.m16n8k16.row.col.f32.f16.f16.f32 "
        "{%0,%1,%2,%3}, {%4,%5,%6,%7}, {%8,%9}, {%0,%1,%2,%3};"
        : "+f"(d[0]), "+f"(d[1]), "+f"(d[2]), "+f"(d[3])
        : "r"(a[0]), "r"(a[1]), "r"(a[2]), "r"(a[3]), "r"(b[0]), "r"(b[1]));
}
__device__ __forceinline__ float silu(float x) {
    return x / (1.f + expf(-x));
}

// ---------------------------------------------------------------------------
__global__ void zero_counts_kernel() {
    if (threadIdx.x < NEXP) g_cnt[threadIdx.x] = 0;
}

// fp32 -> fp16 conversion (RN), float4-vectorized
__global__ void cvt_half_kernel(const float* __restrict__ in, __half* __restrict__ out) {
    size_t i = (size_t)blockIdx.x * 256 + threadIdx.x;   // float4 index
    float4 v = ((const float4*)in)[i];
    ((__half2*)out)[i * 2]     = __floats2half2_rn(v.x, v.y);
    ((__half2*)out)[i * 2 + 1] = __floats2half2_rn(v.z, v.w);
}

// ---------------------------------------------------------------------------
// Router: 1 warp per token. Also emits fp16 copy of h (fused conversion).
// ---------------------------------------------------------------------------
__global__ void router_kernel(const float* __restrict__ h,
                              const float* __restrict__ gate_w,
                              const float* __restrict__ sg_w,
                              float* __restrict__ logits_out) {
    int warp = threadIdx.x >> 5;
    int lane = threadIdx.x & 31;
    int t = blockIdx.x * 4 + warp;
    if (t >= T_TOK) return;

    float acc[9];
#pragma unroll
    for (int i = 0; i < 9; i++) acc[i] = 0.f;

    const float4* hp = (const float4*)(h + (size_t)t * DDIM);
    __half2* hp16 = (__half2*)(g_h16 + (size_t)t * DDIM);
    for (int d = lane; d < DDIM / 4; d += 32) {
        float4 hv = hp[d];
        hp16[d * 2]     = __floats2half2_rn(hv.x, hv.y);
        hp16[d * 2 + 1] = __floats2half2_rn(hv.z, hv.w);
#pragma unroll
        for (int e = 0; e < NEXP; e++) {
            float4 w = ((const float4*)(gate_w + (size_t)e * DDIM))[d];
            acc[e] += hv.x * w.x + hv.y * w.y + hv.z * w.z + hv.w * w.w;
        }
        float4 w = ((const float4*)sg_w)[d];
        acc[8] += hv.x * w.x + hv.y * w.y + hv.z * w.z + hv.w * w.w;
    }
#pragma unroll
    for (int i = 0; i < 9; i++) {
#pragma unroll
        for (int off = 16; off > 0; off >>= 1)
            acc[i] += __shfl_down_sync(0xffffffffu, acc[i], off);
    }

    if (lane == 0) {
        if (logits_out) {
#pragma unroll
            for (int e = 0; e < NEXP; e++) logits_out[t * NEXP + e] = acc[e];
        }
        int i0 = 0;
#pragma unroll
        for (int e = 1; e < NEXP; e++) if (acc[e] > acc[i0]) i0 = e;
        int i1 = (i0 == 0) ? 1 : 0;
#pragma unroll
        for (int e = 0; e < NEXP; e++) if (e != i0 && e != i1 && acc[e] > acc[i1]) i1 = e;

        float wA = 1.f / (1.f + expf(acc[i1] - acc[i0]));
        float wB = 1.f - wA;

        int s0 = atomicAdd(&g_cnt[i0], 1);
        g_tok[i0 * CAP + s0] = t;  g_wt[i0 * CAP + s0] = wA;
        int s1 = atomicAdd(&g_cnt[i1], 1);
        g_tok[i1 * CAP + s1] = t;  g_wt[i1 * CAP + s1] = wB;

        g_gate[t] = 1.f / (1.f + expf(-acc[8]));
    }
}

// ---------------------------------------------------------------------------
// fp16 mma.sync GEMM (m16n8k16), cp.async 2-stage, fused epilogues.
// CTA 128x128, 256 threads = 8 warps (2x4), warp tile 64x32, BKH=32.
// NO in-place buffers: every mode reads one buffer and writes a DIFFERENT one.
// MODE 0: up-routed-g  A=h16 gathered; g_gh[slot,f] = fp16(acc + b0[e,f])
// MODE 1: up-shared-g  A=h16;          g_sgh[t,f]   = fp16(acc + sb0[f])
// MODE 4: up-routed-u  A=h16 gathered; g_ih[slot,f] = fp16(silu(g_gh)*(acc+b1[e,f]))
// MODE 5: up-shared-u  A=h16;          g_sih[t,f]   = fp16(silu(g_sgh)*(acc+sb1[f]))
// MODE 2: down-routed  A=g_ih;  atomicAdd(out[tok,d], wt*(acc+bo[e,d]))
// MODE 3: down-shared  A=g_sih; out[t,d] = gate[t]*(acc+sbo[d])
// ---------------------------------------------------------------------------
template<int MODE>
__global__ void __launch_bounds__(256, 2)
gemm_h(const __half* __restrict__ A, const __half* __restrict__ B,
       const float* __restrict__ bias, float* __restrict__ out) {
    constexpr bool ROUTED = (MODE == 0 || MODE == 2 || MODE == 4);
    constexpr int  K  = (MODE == 2 || MODE == 3) ? FDIM : DDIM;
    constexpr int  NT = K / BKH;
    const int e  = ROUTED ? blockIdx.z : 0;
    const int Ne = ROUTED ? g_cnt[e] : T_TOK;
    const int row0 = blockIdx.y * BM;
    if (row0 >= Ne) return;
    const int n0  = blockIdx.x * BN;
    const int tid  = threadIdx.x;
    const int lane = tid & 31;
    const int wid  = tid >> 5;
    const int wm   = (wid >> 2) * 64;
    const int wn   = (wid & 3) * 32;

    __shared__ uint32_t As[2][BM][SPAD];
    __shared__ uint32_t Bs[2][BN][SPAD];
    __shared__ int   sTok[BM];
    __shared__ float sWt[BM];

    if (ROUTED) {
        if (tid < BM) {
            int r = row0 + tid;
            int rr = (r < Ne) ? r : (Ne - 1);
            sTok[tid] = g_tok[e * CAP + rr];
            sWt[tid]  = g_wt[e * CAP + rr];
        }
        __syncthreads();
    }

    const __half* Bb = (MODE == 0 || MODE == 4) ? (B + (size_t)e * FDIM * DDIM)
                     : (MODE == 2)              ? (B + (size_t)e * DDIM * FDIM)
                     : B;

    float acc[4][4][4];
#pragma unroll
    for (int i = 0; i < 4; i++)
#pragma unroll
        for (int j = 0; j < 4; j++)
#pragma unroll
            for (int r = 0; r < 4; r++) acc[i][j][r] = 0.f;

    // staging: tile = 128 rows x 64B = 512 x 16B chunks; 2 per thread per matrix
    const __half* aptr[2];
    const __half* bptr[2];
    uint32_t      dA[2], dB[2];
#pragma unroll
    for (int i = 0; i < 2; i++) {
        int idx = i * 256 + tid;
        int r  = idx >> 2;
        int ch = (idx & 3) * 8;
        const __half* ap;
        if (MODE == 0 || MODE == 4)      ap = A + (size_t)sTok[r] * DDIM + ch;
        else if (MODE == 1 || MODE == 5) ap = A + (size_t)(row0 + r) * DDIM + ch;
        else if (MODE == 2)              ap = A + ((size_t)e * CAP + row0 + r) * FDIM + ch;
        else                             ap = A + (size_t)(row0 + r) * FDIM + ch;
        aptr[i] = ap;
        bptr[i] = Bb + (size_t)(n0 + r) * K + ch;
        dA[i] = su32(&As[0][r][(idx & 3) * 4]);
        dB[i] = su32(&Bs[0][r][(idx & 3) * 4]);
    }

#pragma unroll
    for (int i = 0; i < 2; i++) {
        cpasync16(dA[i], aptr[i]);
        cpasync16(dB[i], bptr[i]);
    }
    CP_COMMIT();

    for (int it = 0; it < NT; it++) {
        const int buf = it & 1;
        if (it + 1 < NT) {
            const int nbuf = (it + 1) & 1;
            const int koff = (it + 1) * BKH;
#pragma unroll
            for (int i = 0; i < 2; i++) {
                cpasync16(dA[i] + nbuf * SBUF, aptr[i] + koff);
                cpasync16(dB[i] + nbuf * SBUF, bptr[i] + koff);
            }
            CP_COMMIT();
            CP_WAIT(1);
        } else {
            CP_WAIT(0);
        }
        __syncthreads();

        const int lr = lane >> 2, lc = lane & 3;
#pragma unroll
        for (int ks = 0; ks < 2; ks++) {
            const int base = ks * 8;
            uint32_t af[4][4], bf[4][2];
#pragma unroll
            for (int im = 0; im < 4; im++) {
                int rb = wm + im * 16 + lr;
                af[im][0] = As[buf][rb][base + lc];
                af[im][1] = As[buf][rb + 8][base + lc];
                af[im][2] = As[buf][rb][base + lc + 4];
                af[im][3] = As[buf][rb + 8][base + lc + 4];
            }
#pragma unroll
            for (int in = 0; in < 4; in++) {
                int nb = wn + in * 8 + lr;
                bf[in][0] = Bs[buf][nb][base + lc];
                bf[in][1] = Bs[buf][nb][base + lc + 4];
            }
#pragma unroll
            for (int im = 0; im < 4; im++)
#pragma unroll
                for (int in = 0; in < 4; in++)
                    mma16(acc[im][in], af[im], bf[in]);
        }
        __syncthreads();
    }

    // ---- fused epilogues (read buffer != write buffer, no aliasing) ----
    const float* bp = (MODE == 0 || MODE == 4) ? (bias + e * FDIM)
                    : (MODE == 2)              ? (bias + e * DDIM)
                    : bias;
#pragma unroll
    for (int im = 0; im < 4; im++) {
#pragma unroll
        for (int in = 0; in < 4; in++) {
            const int c0 = n0 + wn + in * 8 + 2 * (lane & 3);
            const float b0v = bp[c0], b1v = bp[c0 + 1];
#pragma unroll
            for (int half_row = 0; half_row < 2; half_row++) {
                int r = wm + im * 16 + (lane >> 2) + half_row * 8;
                if (row0 + r >= Ne) continue;
                float v0 = acc[im][in][half_row * 2 + 0] + b0v;
                float v1 = acc[im][in][half_row * 2 + 1] + b1v;
                if (MODE == 0) {
                    size_t idx = ((size_t)e * CAP + row0 + r) * FDIM + c0;
                    *(__half2*)(g_gh + idx) = __floats2half2_rn(v0, v1);
                } else if (MODE == 1) {
                    size_t idx = (size_t)(row0 + r) * FDIM + c0;
                    *(__half2*)(g_sgh + idx) = __floats2half2_rn(v0, v1);
                } else if (MODE == 4) {
                    size_t idx = ((size_t)e * CAP + row0 + r) * FDIM + c0;
                    __half2 gv = *(const __half2*)(g_gh + idx);
                    float r0 = silu(__half2float(__low2half(gv)))  * v0;
                    float r1 = silu(__half2float(__high2half(gv))) * v1;
                    *(__half2*)(g_ih + idx) = __floats2half2_rn(r0, r1);
                } else if (MODE == 5) {
                    size_t idx = (size_t)(row0 + r) * FDIM + c0;
                    __half2 gv = *(const __half2*)(g_sgh + idx);
                    float r0 = silu(__half2float(__low2half(gv)))  * v0;
                    float r1 = silu(__half2float(__high2half(gv))) * v1;
                    *(__half2*)(g_sih + idx) = __floats2half2_rn(r0, r1);
                } else if (MODE == 2) {
                    int   t  = sTok[r];
                    float wt = sWt[r];
                    float* op = out + (size_t)t * DDIM + c0;
                    atomicAdd(op,     wt * v0);
                    atomicAdd(op + 1, wt * v1);
                } else {  // MODE 3
                    float gate = g_gate[row0 + r];
                    *(float2*)(out + (size_t)(row0 + r) * DDIM + c0) =
                        make_float2(gate * v0, gate * v1);
                }
            }
        }
    }
}

// ---------------------------------------------------------------------------
extern "C" void kernel_launch(void* const* d_in, const int* in_sizes, int n_in,
                              void* d_out, int out_size) {
    const float* h      = (const float*)d_in[0];
    const float* gate_w = (const float*)d_in[1];
    const float* w0     = (const float*)d_in[2];
    const float* b0     = (const float*)d_in[3];
    const float* w1     = (const float*)d_in[4];
    const float* b1     = (const float*)d_in[5];
    const float* wo     = (const float*)d_in[6];
    const float* bo     = (const float*)d_in[7];
    const float* sw0    = (const float*)d_in[8];
    const float* sb0    = (const float*)d_in[9];
    const float* sw1    = (const float*)d_in[10];
    const float* sb1    = (const float*)d_in[11];
    const float* swo    = (const float*)d_in[12];
    const float* sbo    = (const float*)d_in[13];
    const float* sg_w   = (const float*)d_in[14];

    float* out = (float*)d_out;
    float* logits = nullptr;
    if ((size_t)out_size >= (size_t)T_TOK * DDIM + (size_t)T_TOK * NEXP)
        logits = out + (size_t)T_TOK * DDIM;

    __half *h16, *w0h, *w1h, *woh, *sw0h, *sw1h, *swoh, *ih, *sih;
    cudaGetSymbolAddress((void**)&h16,  g_h16);
    cudaGetSymbolAddress((void**)&w0h,  g_w0h);
    cudaGetSymbolAddress((void**)&w1h,  g_w1h);
    cudaGetSymbolAddress((void**)&woh,  g_woh);
    cudaGetSymbolAddress((void**)&sw0h, g_sw0h);
    cudaGetSymbolAddress((void**)&sw1h, g_sw1h);
    cudaGetSymbolAddress((void**)&swoh, g_swoh);
    cudaGetSymbolAddress((void**)&ih,   g_ih);
    cudaGetSymbolAddress((void**)&sih,  g_sih);

    zero_counts_kernel<<<1, 32>>>();
    router_kernel<<<T_TOK / 4, 128>>>(h, gate_w, sg_w, logits);   // also emits h16

    // weight fp32 -> fp16 conversion (bandwidth-bound)
    const unsigned NB_W = (unsigned)((size_t)NEXP * FDIM * DDIM / 4 / 256);
    const unsigned NB_S = (unsigned)((size_t)FDIM * DDIM / 4 / 256);
    cvt_half_kernel<<<NB_W, 256>>>(w0,  w0h);
    cvt_half_kernel<<<NB_W, 256>>>(w1,  w1h);
    cvt_half_kernel<<<NB_W, 256>>>(wo,  woh);
    cvt_half_kernel<<<NB_S, 256>>>(sw0, sw0h);
    cvt_half_kernel<<<NB_S, 256>>>(sw1, sw1h);
    cvt_half_kernel<<<NB_S, 256>>>(swo, swoh);

    // up projections: g pass, then u pass with fused SwiGLU epilogue
    gemm_h<0><<<dim3(FDIM / BN, CAP / BM, NEXP), 256>>>(h16, w0h, b0, nullptr);
    gemm_h<4><<<dim3(FDIM / BN, CAP / BM, NEXP), 256>>>(h16, w1h, b1, nullptr);
    gemm_h<1><<<dim3(FDIM / BN, T_TOK / BM, 1), 256>>>(h16, sw0h, sb0, nullptr);
    gemm_h<5><<<dim3(FDIM / BN, T_TOK / BM, 1), 256>>>(h16, sw1h, sb1, nullptr);

    // down projections: shared writes base, routed atomically accumulates
    gemm_h<3><<<dim3(DDIM / BN, T_TOK / BM, 1), 256>>>(sih, swoh, sbo, out);
    gemm_h<2><<<dim3(DDIM / BN, CAP / BM, NEXP), 256>>>(ih, woh, bo, out);
}

// round 11
// speedup vs baseline: 5.6813x; 1.0664x over previous
#include <cuda_runtime.h>
#include <cuda_fp16.h>
#include <math.h>
#include <stdint.h>

#define T_TOK 4096
#define DDIM  2048
#define NEXP  8
#define FDIM  512
#define CAP   4096
#define BM    128
#define BN    128       // down-GEMM N tile
#define BNF   64        // fused up-GEMM N tile
#define BKH   32        // K-chunk in halves (= 64 bytes per row)
#define SPAD  20        // smem row stride in uint32 (16 data + 4 pad)
#define SBUF  (BM * SPAD * 4)    // down: one stage bytes = 10240
#define SBUFA (BM * SPAD * 4)    // fused A stage bytes = 10240
#define SBUFB (BNF * SPAD * 4)   // fused B stage bytes = 5120

// ---------------------------------------------------------------------------
// Scratch (device globals; allocation is forbidden)
// ---------------------------------------------------------------------------
__device__ __half g_h16 [(size_t)T_TOK * DDIM];
__device__ __half g_w0h [(size_t)NEXP * FDIM * DDIM];
__device__ __half g_w1h [(size_t)NEXP * FDIM * DDIM];
__device__ __half g_woh [(size_t)NEXP * DDIM * FDIM];
__device__ __half g_sw0h[(size_t)FDIM * DDIM];
__device__ __half g_sw1h[(size_t)FDIM * DDIM];
__device__ __half g_swoh[(size_t)DDIM * FDIM];
__device__ __half g_ih  [(size_t)NEXP * CAP * FDIM];   // routed silu(g)*u
__device__ __half g_sih [(size_t)T_TOK * FDIM];        // shared silu(g)*u
__device__ int    g_cnt[NEXP];
__device__ int    g_tok[NEXP * CAP];
__device__ float  g_wt[NEXP * CAP];
__device__ float  g_gate[T_TOK];

__device__ __forceinline__ uint32_t su32(const void* p) {
    uint32_t a;
    asm("{ .reg .u64 t; cvta.to.shared.u64 t, %1; cvt.u32.u64 %0, t; }" : "=r"(a) : "l"(p));
    return a;
}
__device__ __forceinline__ void cpasync16(uint32_t dst, const void* src) {
    asm volatile("cp.async.cg.shared.global [%0], [%1], 16;" :: "r"(dst), "l"(src) : "memory");
}
#define CP_COMMIT() asm volatile("cp.async.commit_group;" ::: "memory")
#define CP_WAIT(n)  asm volatile("cp.async.wait_group %0;" :: "n"(n) : "memory")

__device__ __forceinline__ void mma16(float* d, const uint32_t* a, const uint32_t* b) {
    asm volatile(
        "mma.sync.aligned.m16n8k16.row.col.f32.f16.f16.f32 "
        "{%0,%1,%2,%3}, {%4,%5,%6,%7}, {%8,%9}, {%0,%1,%2,%3};"
        : "+f"(d[0]), "+f"(d[1]), "+f"(d[2]), "+f"(d[3])
        : "r"(a[0]), "r"(a[1]), "r"(a[2]), "r"(a[3]), "r"(b[0]), "r"(b[1]));
}
__device__ __forceinline__ float silu(float x) {
    return x / (1.f + expf(-x));
}

// ---------------------------------------------------------------------------
__global__ void zero_counts_kernel() {
    if (threadIdx.x < NEXP) g_cnt[threadIdx.x] = 0;
}

// fp32 -> fp16 conversion (RN), float4-vectorized
__global__ void cvt_half_kernel(const float* __restrict__ in, __half* __restrict__ out) {
    size_t i = (size_t)blockIdx.x * 256 + threadIdx.x;   // float4 index
    float4 v = ((const float4*)in)[i];
    ((__half2*)out)[i * 2]     = __floats2half2_rn(v.x, v.y);
    ((__half2*)out)[i * 2 + 1] = __floats2half2_rn(v.z, v.w);
}

// ---------------------------------------------------------------------------
// Router: 1 warp per token. Also emits fp16 copy of h (fused conversion).
// ---------------------------------------------------------------------------
__global__ void router_kernel(const float* __restrict__ h,
                              const float* __restrict__ gate_w,
                              const float* __restrict__ sg_w,
                              float* __restrict__ logits_out) {
    int warp = threadIdx.x >> 5;
    int lane = threadIdx.x & 31;
    int t = blockIdx.x * 4 + warp;
    if (t >= T_TOK) return;

    float acc[9];
#pragma unroll
    for (int i = 0; i < 9; i++) acc[i] = 0.f;

    const float4* hp = (const float4*)(h + (size_t)t * DDIM);
    __half2* hp16 = (__half2*)(g_h16 + (size_t)t * DDIM);
    for (int d = lane; d < DDIM / 4; d += 32) {
        float4 hv = hp[d];
        hp16[d * 2]     = __floats2half2_rn(hv.x, hv.y);
        hp16[d * 2 + 1] = __floats2half2_rn(hv.z, hv.w);
#pragma unroll
        for (int e = 0; e < NEXP; e++) {
            float4 w = ((const float4*)(gate_w + (size_t)e * DDIM))[d];
            acc[e] += hv.x * w.x + hv.y * w.y + hv.z * w.z + hv.w * w.w;
        }
        float4 w = ((const float4*)sg_w)[d];
        acc[8] += hv.x * w.x + hv.y * w.y + hv.z * w.z + hv.w * w.w;
    }
#pragma unroll
    for (int i = 0; i < 9; i++) {
#pragma unroll
        for (int off = 16; off > 0; off >>= 1)
            acc[i] += __shfl_down_sync(0xffffffffu, acc[i], off);
    }

    if (lane == 0) {
        if (logits_out) {
#pragma unroll
            for (int e = 0; e < NEXP; e++) logits_out[t * NEXP + e] = acc[e];
        }
        int i0 = 0;
#pragma unroll
        for (int e = 1; e < NEXP; e++) if (acc[e] > acc[i0]) i0 = e;
        int i1 = (i0 == 0) ? 1 : 0;
#pragma unroll
        for (int e = 0; e < NEXP; e++) if (e != i0 && e != i1 && acc[e] > acc[i1]) i1 = e;

        float wA = 1.f / (1.f + expf(acc[i1] - acc[i0]));
        float wB = 1.f - wA;

        int s0 = atomicAdd(&g_cnt[i0], 1);
        g_tok[i0 * CAP + s0] = t;  g_wt[i0 * CAP + s0] = wA;
        int s1 = atomicAdd(&g_cnt[i1], 1);
        g_tok[i1 * CAP + s1] = t;  g_wt[i1 * CAP + s1] = wB;

        g_gate[t] = 1.f / (1.f + expf(-acc[8]));
    }
}

// ---------------------------------------------------------------------------
// FUSED up-projection: one pass computes g = A*W0^T+b0 AND u = A*W1^T+b1,
// then writes fp16 silu(g)*u. g/u live only in registers (fp32).
// CTA tile 128(M) x 64(N), 256 threads = 8 warps (4x2), warp tile 32x32 dual.
// ---------------------------------------------------------------------------
template<bool ROUTED>
__global__ void __launch_bounds__(256, 2)
upfused_h(const __half* __restrict__ A,
          const __half* __restrict__ W0g, const float* __restrict__ B0v,
          const __half* __restrict__ W1g, const float* __restrict__ B1v) {
    constexpr int NT = DDIM / BKH;   // 64
    const int e  = ROUTED ? blockIdx.z : 0;
    const int Ne = ROUTED ? g_cnt[e] : T_TOK;
    const int row0 = blockIdx.y * BM;
    if (row0 >= Ne) return;
    const int n0  = blockIdx.x * BNF;
    const int tid  = threadIdx.x;
    const int lane = tid & 31;
    const int wid  = tid >> 5;
    const int wm   = (wid >> 1) * 32;   // 4 warp-rows over M=128
    const int wn   = (wid & 1) * 32;    // 2 warp-cols over N=64

    __shared__ uint32_t As [2][BM][SPAD];
    __shared__ uint32_t Bs0[2][BNF][SPAD];
    __shared__ uint32_t Bs1[2][BNF][SPAD];
    __shared__ int sTok[BM];

    if (ROUTED) {
        if (tid < BM) {
            int r = row0 + tid;
            sTok[tid] = g_tok[e * CAP + ((r < Ne) ? r : (Ne - 1))];
        }
        __syncthreads();
    }

    const __half* W0b = ROUTED ? (W0g + (size_t)e * FDIM * DDIM) : W0g;
    const __half* W1b = ROUTED ? (W1g + (size_t)e * FDIM * DDIM) : W1g;

    float acc0[2][4][4], acc1[2][4][4];
#pragma unroll
    for (int i = 0; i < 2; i++)
#pragma unroll
        for (int j = 0; j < 4; j++)
#pragma unroll
            for (int r = 0; r < 4; r++) { acc0[i][j][r] = 0.f; acc1[i][j][r] = 0.f; }

    // staging: A = 512 chunks (2/thread), B0/B1 = 256 chunks (1/thread)
    const __half* aptr[2];
    uint32_t dAs[2];
#pragma unroll
    for (int i = 0; i < 2; i++) {
        int idx = i * 256 + tid;
        int r  = idx >> 2;
        int ch = (idx & 3) * 8;
        aptr[i] = ROUTED ? (A + (size_t)sTok[r] * DDIM + ch)
                         : (A + (size_t)(row0 + r) * DDIM + ch);
        dAs[i]  = su32(&As[0][r][(idx & 3) * 4]);
    }
    const int br  = tid >> 2;          // 0..63
    const int bch = (tid & 3) * 8;
    const __half* b0ptr = W0b + (size_t)(n0 + br) * DDIM + bch;
    const __half* b1ptr = W1b + (size_t)(n0 + br) * DDIM + bch;
    const uint32_t dB0 = su32(&Bs0[0][br][(tid & 3) * 4]);
    const uint32_t dB1 = su32(&Bs1[0][br][(tid & 3) * 4]);

    // prologue
#pragma unroll
    for (int i = 0; i < 2; i++) cpasync16(dAs[i], aptr[i]);
    cpasync16(dB0, b0ptr);
    cpasync16(dB1, b1ptr);
    CP_COMMIT();

    for (int it = 0; it < NT; it++) {
        const int buf = it & 1;
        if (it + 1 < NT) {
            const int nbuf = (it + 1) & 1;
            const int koff = (it + 1) * BKH;
#pragma unroll
            for (int i = 0; i < 2; i++) cpasync16(dAs[i] + nbuf * SBUFA, aptr[i] + koff);
            cpasync16(dB0 + nbuf * SBUFB, b0ptr + koff);
            cpasync16(dB1 + nbuf * SBUFB, b1ptr + koff);
            CP_COMMIT();
            CP_WAIT(1);
        } else {
            CP_WAIT(0);
        }
        __syncthreads();

        const int lr = lane >> 2, lc = lane & 3;
#pragma unroll
        for (int ks = 0; ks < 2; ks++) {
            const int base = ks * 8;
            uint32_t af[2][4], bf0[4][2], bf1[4][2];
#pragma unroll
            for (int im = 0; im < 2; im++) {
                int rb = wm + im * 16 + lr;
                af[im][0] = As[buf][rb][base + lc];
                af[im][1] = As[buf][rb + 8][base + lc];
                af[im][2] = As[buf][rb][base + lc + 4];
                af[im][3] = As[buf][rb + 8][base + lc + 4];
            }
#pragma unroll
            for (int in = 0; in < 4; in++) {
                int nb = wn + in * 8 + lr;
                bf0[in][0] = Bs0[buf][nb][base + lc];
                bf0[in][1] = Bs0[buf][nb][base + lc + 4];
                bf1[in][0] = Bs1[buf][nb][base + lc];
                bf1[in][1] = Bs1[buf][nb][base + lc + 4];
            }
#pragma unroll
            for (int im = 0; im < 2; im++)
#pragma unroll
                for (int in = 0; in < 4; in++) {
                    mma16(acc0[im][in], af[im], bf0[in]);
                    mma16(acc1[im][in], af[im], bf1[in]);
                }
        }
        __syncthreads();
    }

    // ---- epilogue: SwiGLU fully in registers, fp16 out ----
    const float* b0p = ROUTED ? (B0v + e * FDIM) : B0v;
    const float* b1p = ROUTED ? (B1v + e * FDIM) : B1v;
#pragma unroll
    for (int im = 0; im < 2; im++) {
#pragma unroll
        for (int in = 0; in < 4; in++) {
            const int c0 = n0 + wn + in * 8 + 2 * (lane & 3);
            const float g_b0 = b0p[c0], g_b1 = b0p[c0 + 1];
            const float u_b0 = b1p[c0], u_b1 = b1p[c0 + 1];
#pragma unroll
            for (int hr = 0; hr < 2; hr++) {
                int r = wm + im * 16 + (lane >> 2) + hr * 8;
                if (row0 + r >= Ne) continue;
                float gg0 = acc0[im][in][hr * 2 + 0] + g_b0;
                float gg1 = acc0[im][in][hr * 2 + 1] + g_b1;
                float uu0 = acc1[im][in][hr * 2 + 0] + u_b0;
                float uu1 = acc1[im][in][hr * 2 + 1] + u_b1;
                float r0 = silu(gg0) * uu0;
                float r1 = silu(gg1) * uu1;
                if (ROUTED) {
                    size_t idx = ((size_t)e * CAP + row0 + r) * FDIM + c0;
                    *(__half2*)(g_ih + idx) = __floats2half2_rn(r0, r1);
                } else {
                    size_t idx = (size_t)(row0 + r) * FDIM + c0;
                    *(__half2*)(g_sih + idx) = __floats2half2_rn(r0, r1);
                }
            }
        }
    }
}

// ---------------------------------------------------------------------------
// Down-projection fp16 mma.sync GEMM (m16n8k16), cp.async 2-stage.
// CTA 128x128, 256 threads = 8 warps (2x4), warp tile 64x32, K=FDIM.
// MODE 2: routed  A=g_ih;  atomicAdd(out[tok,d], wt*(acc+bo[e,d]))
// MODE 3: shared  A=g_sih; out[t,d] = gate[t]*(acc+sbo[d])
// ---------------------------------------------------------------------------
template<int MODE>
__global__ void __launch_bounds__(256, 2)
gemm_h(const __half* __restrict__ A, const __half* __restrict__ B,
       const float* __restrict__ bias, float* __restrict__ out) {
    constexpr int K  = FDIM;
    constexpr int NT = K / BKH;   // 16
    const int e  = (MODE == 2) ? blockIdx.z : 0;
    const int Ne = (MODE == 2) ? g_cnt[e] : T_TOK;
    const int row0 = blockIdx.y * BM;
    if (row0 >= Ne) return;
    const int n0  = blockIdx.x * BN;
    const int tid  = threadIdx.x;
    const int lane = tid & 31;
    const int wid  = tid >> 5;
    const int wm   = (wid >> 2) * 64;
    const int wn   = (wid & 3) * 32;

    __shared__ uint32_t As[2][BM][SPAD];
    __shared__ uint32_t Bs[2][BN][SPAD];
    __shared__ int   sTok[BM];
    __shared__ float sWt[BM];

    if (MODE == 2) {
        if (tid < BM) {
            int r = row0 + tid;
            int rr = (r < Ne) ? r : (Ne - 1);
            sTok[tid] = g_tok[e * CAP + rr];
            sWt[tid]  = g_wt[e * CAP + rr];
        }
        __syncthreads();
    }

    const __half* Bb = (MODE == 2) ? (B + (size_t)e * DDIM * FDIM) : B;

    float acc[4][4][4];
#pragma unroll
    for (int i = 0; i < 4; i++)
#pragma unroll
        for (int j = 0; j < 4; j++)
#pragma unroll
            for (int r = 0; r < 4; r++) acc[i][j][r] = 0.f;

    const __half* aptr[2];
    const __half* bptr[2];
    uint32_t      dA[2], dB[2];
#pragma unroll
    for (int i = 0; i < 2; i++) {
        int idx = i * 256 + tid;
        int r  = idx >> 2;
        int ch = (idx & 3) * 8;
        if (MODE == 2) aptr[i] = A + ((size_t)e * CAP + row0 + r) * FDIM + ch;
        else           aptr[i] = A + (size_t)(row0 + r) * FDIM + ch;
        bptr[i] = Bb + (size_t)(n0 + r) * K + ch;
        dA[i] = su32(&As[0][r][(idx & 3) * 4]);
        dB[i] = su32(&Bs[0][r][(idx & 3) * 4]);
    }

#pragma unroll
    for (int i = 0; i < 2; i++) {
        cpasync16(dA[i], aptr[i]);
        cpasync16(dB[i], bptr[i]);
    }
    CP_COMMIT();

    for (int it = 0; it < NT; it++) {
        const int buf = it & 1;
        if (it + 1 < NT) {
            const int nbuf = (it + 1) & 1;
            const int koff = (it + 1) * BKH;
#pragma unroll
            for (int i = 0; i < 2; i++) {
                cpasync16(dA[i] + nbuf * SBUF, aptr[i] + koff);
                cpasync16(dB[i] + nbuf * SBUF, bptr[i] + koff);
            }
            CP_COMMIT();
            CP_WAIT(1);
        } else {
            CP_WAIT(0);
        }
        __syncthreads();

        const int lr = lane >> 2, lc = lane & 3;
#pragma unroll
        for (int ks = 0; ks < 2; ks++) {
            const int base = ks * 8;
            uint32_t af[4][4], bf[4][2];
#pragma unroll
            for (int im = 0; im < 4; im++) {
                int rb = wm + im * 16 + lr;
                af[im][0] = As[buf][rb][base + lc];
                af[im][1] = As[buf][rb + 8][base + lc];
                af[im][2] = As[buf][rb][base + lc + 4];
                af[im][3] = As[buf][rb + 8][base + lc + 4];
            }
#pragma unroll
            for (int in = 0; in < 4; in++) {
                int nb = wn + in * 8 + lr;
                bf[in][0] = Bs[buf][nb][base + lc];
                bf[in][1] = Bs[buf][nb][base + lc + 4];
            }
#pragma unroll
            for (int im = 0; im < 4; im++)
#pragma unroll
                for (int in = 0; in < 4; in++)
                    mma16(acc[im][in], af[im], bf[in]);
        }
        __syncthreads();
    }

    const float* bp = (MODE == 2) ? (bias + e * DDIM) : bias;
#pragma unroll
    for (int im = 0; im < 4; im++) {
#pragma unroll
        for (int in = 0; in < 4; in++) {
            const int c0 = n0 + wn + in * 8 + 2 * (lane & 3);
            const float b0v = bp[c0], b1v = bp[c0 + 1];
#pragma unroll
            for (int hr = 0; hr < 2; hr++) {
                int r = wm + im * 16 + (lane >> 2) + hr * 8;
                if (row0 + r >= Ne) continue;
                float v0 = acc[im][in][hr * 2 + 0] + b0v;
                float v1 = acc[im][in][hr * 2 + 1] + b1v;
                if (MODE == 2) {
                    int   t  = sTok[r];
                    float wt = sWt[r];
                    float* op = out + (size_t)t * DDIM + c0;
                    atomicAdd(op,     wt * v0);
                    atomicAdd(op + 1, wt * v1);
                } else {
                    float gate = g_gate[row0 + r];
                    *(float2*)(out + (size_t)(row0 + r) * DDIM + c0) =
                        make_float2(gate * v0, gate * v1);
                }
            }
        }
    }
}

// ---------------------------------------------------------------------------
extern "C" void kernel_launch(void* const* d_in, const int* in_sizes, int n_in,
                              void* d_out, int out_size) {
    const float* h      = (const float*)d_in[0];
    const float* gate_w = (const float*)d_in[1];
    const float* w0     = (const float*)d_in[2];
    const float* b0     = (const float*)d_in[3];
    const float* w1     = (const float*)d_in[4];
    const float* b1     = (const float*)d_in[5];
    const float* wo     = (const float*)d_in[6];
    const float* bo     = (const float*)d_in[7];
    const float* sw0    = (const float*)d_in[8];
    const float* sb0    = (const float*)d_in[9];
    const float* sw1    = (const float*)d_in[10];
    const float* sb1    = (const float*)d_in[11];
    const float* swo    = (const float*)d_in[12];
    const float* sbo    = (const float*)d_in[13];
    const float* sg_w   = (const float*)d_in[14];

    float* out = (float*)d_out;
    float* logits = nullptr;
    if ((size_t)out_size >= (size_t)T_TOK * DDIM + (size_t)T_TOK * NEXP)
        logits = out + (size_t)T_TOK * DDIM;

    __half *h16, *w0h, *w1h, *woh, *sw0h, *sw1h, *swoh, *ih, *sih;
    cudaGetSymbolAddress((void**)&h16,  g_h16);
    cudaGetSymbolAddress((void**)&w0h,  g_w0h);
    cudaGetSymbolAddress((void**)&w1h,  g_w1h);
    cudaGetSymbolAddress((void**)&woh,  g_woh);
    cudaGetSymbolAddress((void**)&sw0h, g_sw0h);
    cudaGetSymbolAddress((void**)&sw1h, g_sw1h);
    cudaGetSymbolAddress((void**)&swoh, g_swoh);
    cudaGetSymbolAddress((void**)&ih,   g_ih);
    cudaGetSymbolAddress((void**)&sih,  g_sih);

    zero_counts_kernel<<<1, 32>>>();
    router_kernel<<<T_TOK / 4, 128>>>(h, gate_w, sg_w, logits);   // also emits h16

    // weight fp32 -> fp16 conversion (bandwidth-bound)
    const unsigned NB_W = (unsigned)((size_t)NEXP * FDIM * DDIM / 4 / 256);
    const unsigned NB_S = (unsigned)((size_t)FDIM * DDIM / 4 / 256);
    cvt_half_kernel<<<NB_W, 256>>>(w0,  w0h);
    cvt_half_kernel<<<NB_W, 256>>>(w1,  w1h);
    cvt_half_kernel<<<NB_W, 256>>>(wo,  woh);
    cvt_half_kernel<<<NB_S, 256>>>(sw0, sw0h);
    cvt_half_kernel<<<NB_S, 256>>>(sw1, sw1h);
    cvt_half_kernel<<<NB_S, 256>>>(swo, swoh);

    // fused up projections (g and u in one pass, SwiGLU in registers)
    upfused_h<true> <<<dim3(FDIM / BNF, CAP / BM, NEXP), 256>>>(h16, w0h, b0, w1h, b1);
    upfused_h<false><<<dim3(FDIM / BNF, T_TOK / BM, 1), 256>>>(h16, sw0h, sb0, sw1h, sb1);

    // down projections: shared writes base, routed atomically accumulates
    gemm_h<3><<<dim3(DDIM / BN, T_TOK / BM, 1), 256>>>(sih, swoh, sbo, out);
    gemm_h<2><<<dim3(DDIM / BN, CAP / BM, NEXP), 256>>>(ih, woh, bo, out);
}